// round 6
// baseline (speedup 1.0000x reference)
#include <cuda_runtime.h>
#include <cstdint>
#include <math.h>

#define BB 256
#define CC 256
#define NN 196
#define MM (BB*NN)        // 50176
#define CMID 2048
#define EPSL 1e-5f

#if defined(__CUDA_ARCH_FEAT_SM103_ALL) || defined(__CUDA_ARCH_FEAT_SM100_ALL) || defined(__CUDA_ARCH_FEAT_SM101_ALL)
#define TC_OK 1
#else
#define TC_OK 0
#endif

// ---------------- scratch (device globals) -----------------------------------
__device__ float g_t   [(size_t)MM*CC];
__device__ float g_qkv [(size_t)MM*3*CC];
__device__ float g_attn[(size_t)MM*CC];
__device__ float g_t1  [(size_t)MM*CC];
__device__ float g_wqkvT[(size_t)3*CC*CC];   // [768,256]
__device__ float g_wprojT[(size_t)CC*CC];    // [256,256]
__device__ float g_w1T  [(size_t)CMID*CC];   // [2048,256]
__device__ float g_w2T  [(size_t)CC*CMID];   // [256,2048]

// ---------------- PTX helpers -------------------------------------------------
__device__ __forceinline__ uint32_t smem_u32(const void* p) {
    uint32_t a;
    asm("{ .reg .u64 t; cvta.to.shared.u64 t, %1; cvt.u32.u64 %0, t; }" : "=r"(a) : "l"(p));
    return a;
}

#define MBAR_INIT(addr, cnt) \
    asm volatile("mbarrier.init.shared.b64 [%0], %1;" :: "r"(addr), "r"(cnt) : "memory")

#define MBAR_WAIT(addr, parity) do {                                              \
    uint32_t _m = (addr); uint32_t _p = (parity); uint32_t _d;                    \
    asm volatile("{\n\t.reg .pred p;\n\t"                                         \
        "mbarrier.try_wait.parity.acquire.cta.shared::cta.b64 p, [%1], %2;\n\t"   \
        "selp.b32 %0, 1, 0, p;\n\t}" : "=r"(_d) : "r"(_m), "r"(_p) : "memory");   \
    if (!_d) {                                                                     \
        asm volatile("{\n\t.reg .pred P1;\n\t"                                     \
            "W_%=:\n\t"                                                            \
            "mbarrier.try_wait.parity.acquire.cta.shared::cta.b64 P1, [%0], %1, 0x989680;\n\t" \
            "@P1 bra.uni D_%=;\n\t"                                                \
            "bra.uni W_%=;\n\t"                                                    \
            "D_%=:\n\t}" :: "r"(_m), "r"(_p) : "memory");                          \
    } } while (0)

#if TC_OK
__device__ __forceinline__ void mma_tf32(uint32_t d, uint64_t ad, uint64_t bd,
                                         uint32_t idesc, bool acc) {
    uint32_t e = acc ? 1u : 0u;
    asm volatile(
        "{\n\t.reg .pred p;\n\tsetp.ne.u32 p, %5, 0;\n\t"
        "tcgen05.mma.cta_group::1.kind::tf32 [%0], %1, %2, %3, {%4, %4, %4, %4}, p;\n\t}"
        :: "r"(d), "l"(ad), "l"(bd), "r"(idesc), "r"(0u), "r"(e) : "memory");
}

#define LDTM_X32(r, addr)                                                         \
    asm volatile("tcgen05.ld.sync.aligned.32x32b.x32.b32 "                        \
        "{%0, %1, %2, %3, %4, %5, %6, %7, %8, %9, %10, %11, %12, %13, %14, %15, " \
        " %16, %17, %18, %19, %20, %21, %22, %23, %24, %25, %26, %27, %28, %29, %30, %31}, [%32];" \
        : "=r"((r)[0]), "=r"((r)[1]), "=r"((r)[2]), "=r"((r)[3]),                 \
          "=r"((r)[4]), "=r"((r)[5]), "=r"((r)[6]), "=r"((r)[7]),                 \
          "=r"((r)[8]), "=r"((r)[9]), "=r"((r)[10]), "=r"((r)[11]),               \
          "=r"((r)[12]), "=r"((r)[13]), "=r"((r)[14]), "=r"((r)[15]),             \
          "=r"((r)[16]), "=r"((r)[17]), "=r"((r)[18]), "=r"((r)[19]),             \
          "=r"((r)[20]), "=r"((r)[21]), "=r"((r)[22]), "=r"((r)[23]),             \
          "=r"((r)[24]), "=r"((r)[25]), "=r"((r)[26]), "=r"((r)[27]),             \
          "=r"((r)[28]), "=r"((r)[29]), "=r"((r)[30]), "=r"((r)[31])              \
        : "r"(addr))
#endif

static constexpr uint64_t DESC_BASE =
    (uint64_t(2) << 61) | (uint64_t(1) << 46) | (uint64_t(64) << 32) | (uint64_t(1) << 16);

// ---------------- transpose x [B][C][N] -> t [B*N][C] -------------------------
__global__ void k_in_transpose(const float* __restrict__ x, float* __restrict__ t) {
    __shared__ float tile[32][33];
    int b = blockIdx.z;
    int n0 = blockIdx.x * 32, c0 = blockIdx.y * 32;
    int tx = threadIdx.x, ty = threadIdx.y;
    const float* xb = x + (size_t)b * CC * NN;
    #pragma unroll
    for (int j = 0; j < 32; j += 8) {
        int c = c0 + ty + j, n = n0 + tx;
        if (n < NN) tile[ty + j][tx] = xb[(size_t)c * NN + n];
    }
    __syncthreads();
    #pragma unroll
    for (int j = 0; j < 32; j += 8) {
        int n = n0 + ty + j, c = c0 + tx;
        if (n < NN) t[((size_t)b * NN + n) * CC + c] = tile[tx][ty + j];
    }
}

// ---------------- weight transpose W[R,C] -> Wt[C,R] --------------------------
__global__ void k_wt(const float* __restrict__ W, float* __restrict__ Wt, int R, int C) {
    __shared__ float tile[32][33];
    int c0 = blockIdx.x * 32, r0 = blockIdx.y * 32;
    int tx = threadIdx.x, ty = threadIdx.y;
    #pragma unroll
    for (int j = 0; j < 32; j += 8)
        tile[ty + j][tx] = W[(size_t)(r0 + ty + j) * C + c0 + tx];
    __syncthreads();
    #pragma unroll
    for (int j = 0; j < 32; j += 8)
        Wt[(size_t)(c0 + ty + j) * R + r0 + tx] = tile[tx][ty + j];
}

// ---------------- tcgen05 tf32 GEMM (QKV / proj): out = A @ Bt^T + epilogue ---
// epi 0: +bias ;  epi 1: +bias, y = res + v, repbn(y)
__global__ __launch_bounds__(256)
void k_tgemm(const float* __restrict__ A, const float* __restrict__ Bt,
             const float* __restrict__ bias, float* __restrict__ out,
             int M, int N, int K, int epi,
             const float* __restrict__ res,
             const float* __restrict__ gam, const float* __restrict__ bet,
             const float* __restrict__ rm,  const float* __restrict__ rv,
             const float* __restrict__ alpha)
{
#if TC_OK
    extern __shared__ char smem_raw[];
    __shared__ uint64_t s_mbar[2];
    __shared__ uint32_t s_tmem;

    uint32_t sb_raw = smem_u32(smem_raw);
    uint32_t tbase = (sb_raw + 1023u) & ~1023u;
    char* tptr = smem_raw + (tbase - sb_raw);

    int tid = threadIdx.x;
    int wid = tid >> 5, lid = tid & 31;
    int m0 = blockIdx.y * 128, n0 = blockIdx.x * 128;

    if (wid == 0)
        asm volatile("tcgen05.alloc.cta_group::1.sync.aligned.shared::cta.b32 [%0], %1;"
                     :: "r"(smem_u32(&s_tmem)), "r"(128) : "memory");
    if (tid == 0) {
        MBAR_INIT(smem_u32(&s_mbar[0]), 1);
        MBAR_INIT(smem_u32(&s_mbar[1]), 1);
    }
    __syncthreads();
    uint32_t tmem = s_tmem;
    if (wid == 0)
        asm volatile("tcgen05.relinquish_alloc_permit.cta_group::1.sync.aligned;");

    const uint32_t IDESC = (1u << 4) | (2u << 7) | (2u << 10) | (16u << 17) | (8u << 24);
    const int KC = K >> 5;
    int ph0 = 0, ph1 = 0;

    int row_ = tid >> 3, c4_ = tid & 7;
    uint32_t bo0 = row_ * 128 + c4_ * 16;
    uint32_t sw0 = bo0 ^ ((bo0 >> 3) & 0x70);

    float4 avr[4], bvr[4];
    {
        const float* Ag = A + (size_t)m0 * K;
        const float* Bg = Bt + (size_t)n0 * K;
        #pragma unroll
        for (int i = 0; i < 4; i++) {
            int row = row_ + i * 32;
            avr[i] = *(const float4*)(Ag + (size_t)row * K + c4_ * 4);
            bvr[i] = *(const float4*)(Bg + (size_t)row * K + c4_ * 4);
        }
    }

    for (int kc = 0; kc < KC; kc++) {
        int buf = kc & 1;
        uint32_t mb = smem_u32(&s_mbar[buf]);
        if (kc >= 2) {
            if (buf == 0) { MBAR_WAIT(mb, ph0); ph0 ^= 1; }
            else          { MBAR_WAIT(mb, ph1); ph1 ^= 1; }
        }
        char* tA = tptr + buf * 32768;
        char* tB = tA + 16384;
        #pragma unroll
        for (int i = 0; i < 4; i++) {
            uint32_t sw = sw0 + i * 4096;
            *(float4*)(tA + sw) = avr[i];
            *(float4*)(tB + sw) = bvr[i];
        }
        asm volatile("fence.proxy.async.shared::cta;" ::: "memory");
        __syncthreads();
        if (tid == 0) {
            uint32_t sA = tbase + buf * 32768;
            uint32_t sB = sA + 16384;
            uint64_t ad = DESC_BASE | ((uint64_t)(sA >> 4) & 0x3FFF);
            uint64_t bd = DESC_BASE | ((uint64_t)(sB >> 4) & 0x3FFF);
            #pragma unroll
            for (int s = 0; s < 4; s++)
                mma_tf32(tmem, ad + s * 2, bd + s * 2, IDESC, (kc > 0) || (s > 0));
            asm volatile(
                "tcgen05.commit.cta_group::1.mbarrier::arrive::one.shared::cluster.b64 [%0];"
                :: "r"(mb) : "memory");
        }
        if (kc + 1 < KC) {
            const float* Ag = A + (size_t)m0 * K + (kc + 1) * 32;
            const float* Bg = Bt + (size_t)n0 * K + (kc + 1) * 32;
            #pragma unroll
            for (int i = 0; i < 4; i++) {
                int row = row_ + i * 32;
                avr[i] = *(const float4*)(Ag + (size_t)row * K + c4_ * 4);
                bvr[i] = *(const float4*)(Bg + (size_t)row * K + c4_ * 4);
            }
        }
    }

    {
        int lb = (KC - 1) & 1;
        uint32_t mb = smem_u32(&s_mbar[lb]);
        if (lb == 0) { MBAR_WAIT(mb, ph0); }
        else         { MBAR_WAIT(mb, ph1); }
    }
    asm volatile("tcgen05.fence::after_thread_sync;" ::: "memory");
    __syncthreads();

    if (wid < 4) {
        float* spatch = (float*)tptr + wid * (32 * 33);
        int mrow = m0 + wid * 32;
        float alphav = (epi == 1) ? alpha[0] : 0.f;
        for (int c0 = 0; c0 < 128; c0 += 32) {
            uint32_t r[32];
            LDTM_X32(r, tmem + c0);
            asm volatile("tcgen05.wait::ld.sync.aligned;" ::: "memory");
            #pragma unroll
            for (int j = 0; j < 32; j++) spatch[lid * 33 + j] = __uint_as_float(r[j]);
            __syncwarp();
            #pragma unroll
            for (int i = 0; i < 8; i++) {
                int rr = i * 4 + (lid >> 3);
                int c4 = (lid & 7) * 4;
                int m = mrow + rr;
                int n = n0 + c0 + c4;
                float vv[4];
                #pragma unroll
                for (int e = 0; e < 4; e++) vv[e] = spatch[rr * 33 + c4 + e];
                float4 bb = *(const float4*)(bias + n);
                vv[0] += bb.x; vv[1] += bb.y; vv[2] += bb.z; vv[3] += bb.w;
                if (epi == 1) {
                    float4 r4 = *(const float4*)(res + (size_t)m * N + n);
                    float4 g4 = *(const float4*)(gam + n);
                    float4 b4 = *(const float4*)(bet + n);
                    float4 u4 = *(const float4*)(rm + n);
                    float4 s4 = *(const float4*)(rv + n);
                    float y;
                    y = r4.x + vv[0]; vv[0] = (y - u4.x) * (g4.x * rsqrtf(s4.x + EPSL)) + b4.x + alphav * y;
                    y = r4.y + vv[1]; vv[1] = (y - u4.y) * (g4.y * rsqrtf(s4.y + EPSL)) + b4.y + alphav * y;
                    y = r4.z + vv[2]; vv[2] = (y - u4.z) * (g4.z * rsqrtf(s4.z + EPSL)) + b4.z + alphav * y;
                    y = r4.w + vv[3]; vv[3] = (y - u4.w) * (g4.w * rsqrtf(s4.w + EPSL)) + b4.w + alphav * y;
                }
                *(float4*)(out + (size_t)m * N + n) = make_float4(vv[0], vv[1], vv[2], vv[3]);
            }
            __syncwarp();
        }
    }
    __syncthreads();
    if (tid == 0) {
        asm volatile("mbarrier.inval.shared.b64 [%0];" :: "r"(smem_u32(&s_mbar[0])) : "memory");
        asm volatile("mbarrier.inval.shared.b64 [%0];" :: "r"(smem_u32(&s_mbar[1])) : "memory");
    }
    __syncthreads();
    if (wid == 0)
        asm volatile("tcgen05.dealloc.cta_group::1.sync.aligned.b32 %0, %1;"
                     :: "r"(tmem), "r"(128));
#endif
}

// ---------------- fused FFN: t1 -> W1+silu -> W2 -> repbn2 -> out[B,C,N] ------
// smem layout (1KB aligned): A dbuf 2x16K @0, W1 dbuf 2x16K @32K,
//                            hS 4x16K @64K, W2 dbuf 2x32K @128K   (=192KB)
__global__ __launch_bounds__(256)
void k_ffn(const float* __restrict__ t1, const float* __restrict__ W1T,
           const float* __restrict__ b1v, const float* __restrict__ W2T,
           const float* __restrict__ b2v,
           const float* __restrict__ saw, const float* __restrict__ sab,
           const float* __restrict__ gam, const float* __restrict__ bet,
           const float* __restrict__ rm,  const float* __restrict__ rv,
           const float* __restrict__ alpha, float* __restrict__ outBCN)
{
#if TC_OK
    extern __shared__ char smem_raw[];
    __shared__ uint64_t s_mbar[6];   // 0,1:g1  2,3:w2  4:hdone  5:g2done
    __shared__ uint32_t s_tmem;

    uint32_t sb_raw = smem_u32(smem_raw);
    uint32_t tbase = (sb_raw + 1023u) & ~1023u;
    char* tptr = smem_raw + (tbase - sb_raw);

    int tid = threadIdx.x;
    int wid = tid >> 5, lid = tid & 31;
    int m0 = blockIdx.x * 128;

    if (wid == 0)
        asm volatile("tcgen05.alloc.cta_group::1.sync.aligned.shared::cta.b32 [%0], %1;"
                     :: "r"(smem_u32(&s_tmem)), "r"(512) : "memory");
    if (tid == 0)
        for (int i = 0; i < 6; i++) MBAR_INIT(smem_u32(&s_mbar[i]), 1);
    __syncthreads();
    uint32_t tmem = s_tmem;
    if (wid == 0)
        asm volatile("tcgen05.relinquish_alloc_permit.cta_group::1.sync.aligned;");

    const uint32_t IDESC1 = (1u << 4) | (2u << 7) | (2u << 10) | (16u << 17) | (8u << 24); // N=128
    const uint32_t IDESC2 = (1u << 4) | (2u << 7) | (2u << 10) | (32u << 17) | (8u << 24); // N=256
    const uint32_t TM_OUT = tmem;            // cols 0..255
    int ph_g1[2] = {0, 0}, ph_w2[2] = {0, 0};
    int ph_hd = 0, ph_g2d = 0;

    int row_ = tid >> 3, c4_ = tid & 7;
    uint32_t bo0 = row_ * 128 + c4_ * 16;
    uint32_t sw0 = bo0 ^ ((bo0 >> 3) & 0x70);

    for (int i = 0; i < 16; i++) {
        uint32_t htm = tmem + 256 + (i & 1) * 128;   // h accumulator (128 cols)

        // ---- gemm1: h = t1_tile @ W1T[i*128 .. i*128+128)^T ----
        for (int kc = 0; kc < 8; kc++) {
            int buf = kc & 1;
            uint32_t mb = smem_u32(&s_mbar[buf]);
            if (i > 0 || kc >= 2) { MBAR_WAIT(mb, ph_g1[buf]); ph_g1[buf] ^= 1; }
            char* tA = tptr + buf * 16384;
            char* tW = tptr + 32768 + buf * 16384;
            const float* Ag = t1 + (size_t)m0 * 256 + kc * 32;
            const float* Wg = W1T + (size_t)(i * 128) * 256 + kc * 32;
            #pragma unroll
            for (int q = 0; q < 4; q++) {
                int row = row_ + q * 32;
                float4 av = *(const float4*)(Ag + (size_t)row * 256 + c4_ * 4);
                float4 wv = *(const float4*)(Wg + (size_t)row * 256 + c4_ * 4);
                uint32_t sw = sw0 + q * 4096;
                *(float4*)(tA + sw) = av;
                *(float4*)(tW + sw) = wv;
            }
            asm volatile("fence.proxy.async.shared::cta;" ::: "memory");
            __syncthreads();
            if (tid == 0) {
                uint64_t ad = DESC_BASE | ((uint64_t)((tbase + buf * 16384) >> 4) & 0x3FFF);
                uint64_t wd = DESC_BASE | ((uint64_t)((tbase + 32768 + buf * 16384) >> 4) & 0x3FFF);
                #pragma unroll
                for (int s = 0; s < 4; s++)
                    mma_tf32(htm, ad + s * 2, wd + s * 2, IDESC1, (kc > 0) || (s > 0));
                asm volatile(
                    "tcgen05.commit.cta_group::1.mbarrier::arrive::one.shared::cluster.b64 [%0];"
                    :: "r"(mb) : "memory");
            }
        }
        if (tid == 0)
            asm volatile(
                "tcgen05.commit.cta_group::1.mbarrier::arrive::one.shared::cluster.b64 [%0];"
                :: "r"(smem_u32(&s_mbar[4])) : "memory");
        MBAR_WAIT(smem_u32(&s_mbar[4]), ph_hd); ph_hd ^= 1;
        if (i > 0) { MBAR_WAIT(smem_u32(&s_mbar[5]), ph_g2d); ph_g2d ^= 1; }  // hS free
        asm volatile("tcgen05.fence::after_thread_sync;" ::: "memory");

        // ---- drain h: +b1, SpatialSILU, store swizzled into hS ----
        if (wid < 4) {
            int lr = wid * 32 + lid;
            int mg = m0 + lr;
            float sw_ = saw[mg / NN], sbv = sab[mg / NN];
            char* hS = tptr + 65536;
            uint32_t rbo = lr * 128;
            for (int cb = 0; cb < 4; cb++) {
                uint32_t r[32];
                LDTM_X32(r, htm + cb * 32);
                asm volatile("tcgen05.wait::ld.sync.aligned;" ::: "memory");
                float hv[32];
                const float* bb = b1v + i * 128 + cb * 32;
                #pragma unroll
                for (int j = 0; j < 32; j++) {
                    float v = __uint_as_float(r[j]) + bb[j];
                    float w = sw_ * v + sbv;
                    hv[j] = v / (1.f + __expf(-w * v));
                }
                char* dst = hS + cb * 16384;
                #pragma unroll
                for (int j4 = 0; j4 < 8; j4++) {
                    uint32_t bo = rbo + j4 * 16;
                    uint32_t sw = bo ^ ((bo >> 3) & 0x70);
                    *(float4*)(dst + sw) = make_float4(hv[j4*4], hv[j4*4+1], hv[j4*4+2], hv[j4*4+3]);
                }
            }
            asm volatile("tcgen05.fence::before_thread_sync;" ::: "memory");
        }

        // ---- gemm2: out += h @ W2T[:, i*128 .. )^T  (N=256) ----
        for (int ks = 0; ks < 4; ks++) {
            int wbuf = ks & 1;
            uint32_t mb = smem_u32(&s_mbar[2 + wbuf]);
            if (i > 0 || ks >= 2) { MBAR_WAIT(mb, ph_w2[wbuf]); ph_w2[wbuf] ^= 1; }
            char* tW2 = tptr + 131072 + wbuf * 32768;
            const float* Wg = W2T + (size_t)0 * CMID + i * 128 + ks * 32;
            #pragma unroll
            for (int q = 0; q < 8; q++) {
                int row = row_ + q * 32;   // n row 0..255
                float4 wv = *(const float4*)(Wg + (size_t)row * CMID + c4_ * 4);
                uint32_t bo = row * 128 + c4_ * 16;
                uint32_t sw = bo ^ ((bo >> 3) & 0x70);
                *(float4*)(tW2 + sw) = wv;
            }
            asm volatile("fence.proxy.async.shared::cta;" ::: "memory");
            __syncthreads();
            if (tid == 0) {
                uint64_t ad = DESC_BASE | ((uint64_t)((tbase + 65536 + ks * 16384) >> 4) & 0x3FFF);
                uint64_t wd = DESC_BASE | ((uint64_t)((tbase + 131072 + wbuf * 32768) >> 4) & 0x3FFF);
                #pragma unroll
                for (int s = 0; s < 4; s++)
                    mma_tf32(TM_OUT, ad + s * 2, wd + s * 2, IDESC2,
                             !(i == 0 && ks == 0 && s == 0));
                asm volatile(
                    "tcgen05.commit.cta_group::1.mbarrier::arrive::one.shared::cluster.b64 [%0];"
                    :: "r"(mb) : "memory");
            }
        }
        if (tid == 0)
            asm volatile(
                "tcgen05.commit.cta_group::1.mbarrier::arrive::one.shared::cluster.b64 [%0];"
                :: "r"(smem_u32(&s_mbar[5])) : "memory");
    }
    MBAR_WAIT(smem_u32(&s_mbar[5]), ph_g2d);
    asm volatile("tcgen05.fence::after_thread_sync;" ::: "memory");
    __syncthreads();

    // ---- epilogue: +b2, residual t1, repbn2, write out in [B,C,N] layout ----
    if (wid < 4) {
        float* spatch = (float*)tptr + wid * (32 * 33);
        int mrow = m0 + wid * 32;
        float alphav = alpha[0];
        int m_out = mrow + lid;
        int b_o = m_out / NN, nsp = m_out % NN;
        size_t obase = (size_t)b_o * CC * NN + nsp;
        for (int c0 = 0; c0 < 256; c0 += 32) {
            uint32_t r[32];
            LDTM_X32(r, TM_OUT + c0);
            asm volatile("tcgen05.wait::ld.sync.aligned;" ::: "memory");
            #pragma unroll
            for (int j = 0; j < 32; j++) spatch[lid * 33 + j] = __uint_as_float(r[j]);
            __syncwarp();
            #pragma unroll
            for (int q = 0; q < 8; q++) {
                int rr = q * 4 + (lid >> 3);
                int c4 = (lid & 7) * 4;
                int m = mrow + rr;
                int n = c0 + c4;
                float vv[4];
                #pragma unroll
                for (int e = 0; e < 4; e++) vv[e] = spatch[rr * 33 + c4 + e];
                float4 bb = *(const float4*)(b2v + n);
                float4 r4 = *(const float4*)(t1 + (size_t)m * CC + n);
                float4 g4 = *(const float4*)(gam + n);
                float4 b4 = *(const float4*)(bet + n);
                float4 u4 = *(const float4*)(rm + n);
                float4 s4 = *(const float4*)(rv + n);
                float y;
                y = r4.x + vv[0] + bb.x; vv[0] = (y - u4.x) * (g4.x * rsqrtf(s4.x + EPSL)) + b4.x + alphav * y;
                y = r4.y + vv[1] + bb.y; vv[1] = (y - u4.y) * (g4.y * rsqrtf(s4.y + EPSL)) + b4.y + alphav * y;
                y = r4.z + vv[2] + bb.z; vv[2] = (y - u4.z) * (g4.z * rsqrtf(s4.z + EPSL)) + b4.z + alphav * y;
                y = r4.w + vv[3] + bb.w; vv[3] = (y - u4.w) * (g4.w * rsqrtf(s4.w + EPSL)) + b4.w + alphav * y;
                #pragma unroll
                for (int e = 0; e < 4; e++) spatch[rr * 33 + c4 + e] = vv[e];
            }
            __syncwarp();
            #pragma unroll
            for (int cc = 0; cc < 32; cc++)
                outBCN[obase + (size_t)(c0 + cc) * NN] = spatch[lid * 33 + cc];
            __syncwarp();
        }
    }
    __syncthreads();
    if (tid == 0)
        for (int i = 0; i < 6; i++)
            asm volatile("mbarrier.inval.shared.b64 [%0];" :: "r"(smem_u32(&s_mbar[i])) : "memory");
    __syncthreads();
    if (wid == 0)
        asm volatile("tcgen05.dealloc.cta_group::1.sync.aligned.b32 %0, %1;"
                     :: "r"(tmem), "r"(512));
#endif
}

// ---------------- attention: one block per (head, batch) ----------------------
__global__ void k_attn(const float* __restrict__ qkv, float* __restrict__ attnout) {
    extern __shared__ float sh[];
    float4* Ks = (float4*)sh;
    float4* Vs = (float4*)(sh + NN * 32);
    int h = blockIdx.x, b = blockIdx.y;
    int tid = threadIdx.x;
    size_t base = (size_t)b * NN * 768;
    int koff = 256 + h * 32, voff = 512 + h * 32;
    for (int i = tid; i < NN * 8; i += 256) {
        int m = i >> 3, d = i & 7;
        Ks[i] = *(const float4*)(qkv + base + (size_t)m * 768 + koff + d * 4);
        Vs[i] = *(const float4*)(qkv + base + (size_t)m * 768 + voff + d * 4);
    }
    __syncthreads();
    if (tid < NN) {
        float4 q4[8], o4[8];
        const float* qp = qkv + base + (size_t)tid * 768 + h * 32;
        #pragma unroll
        for (int i = 0; i < 8; i++) {
            float4 qv = *(const float4*)(qp + i * 4);
            const float sc = 0.17677669529663687f;
            q4[i] = make_float4(qv.x * sc, qv.y * sc, qv.z * sc, qv.w * sc);
            o4[i] = make_float4(0.f, 0.f, 0.f, 0.f);
        }
        float mx = -1e30f, l = 0.f;
        for (int m = 0; m < NN; m += 2) {
            const float4* k0 = Ks + m * 8;
            const float4* k1 = k0 + 8;
            float s0 = 0.f, s1 = 0.f;
            #pragma unroll
            for (int i = 0; i < 8; i++) {
                float4 a = q4[i], x0 = k0[i], x1 = k1[i];
                s0 += a.x * x0.x + a.y * x0.y + a.z * x0.z + a.w * x0.w;
                s1 += a.x * x1.x + a.y * x1.y + a.z * x1.z + a.w * x1.w;
            }
            float nm = fmaxf(mx, fmaxf(s0, s1));
            float f  = __expf(mx - nm);
            float p0 = __expf(s0 - nm);
            float p1 = __expf(s1 - nm);
            l = l * f + p0 + p1;
            const float4* v0 = Vs + m * 8;
            const float4* v1 = v0 + 8;
            #pragma unroll
            for (int i = 0; i < 8; i++) {
                float4 o = o4[i], a = v0[i], c = v1[i];
                o.x = o.x * f + p0 * a.x + p1 * c.x;
                o.y = o.y * f + p0 * a.y + p1 * c.y;
                o.z = o.z * f + p0 * a.z + p1 * c.z;
                o.w = o.w * f + p0 * a.w + p1 * c.w;
                o4[i] = o;
            }
            mx = nm;
        }
        float inv = 1.f / l;
        float* op = attnout + ((size_t)(b * NN + tid)) * CC + h * 32;
        #pragma unroll
        for (int i = 0; i < 8; i++) {
            float4 o = o4[i];
            *(float4*)(op + i * 4) = make_float4(o.x * inv, o.y * inv, o.z * inv, o.w * inv);
        }
    }
}

// ---------------- launch ------------------------------------------------------
extern "C" void kernel_launch(void* const* d_in, const int* in_sizes, int n_in,
                              void* d_out, int out_size) {
    const float* x      = (const float*)d_in[0];
    const float* W_qkv  = (const float*)d_in[1];
    const float* b_qkv  = (const float*)d_in[2];
    const float* W_proj = (const float*)d_in[3];
    const float* b_proj = (const float*)d_in[4];
    const float* W1     = (const float*)d_in[5];
    const float* b1     = (const float*)d_in[6];
    const float* W2     = (const float*)d_in[7];
    const float* b2     = (const float*)d_in[8];
    const float* sa_w   = (const float*)d_in[9];
    const float* sa_b   = (const float*)d_in[10];
    const float* alpha1 = (const float*)d_in[11];
    const float* gamma1 = (const float*)d_in[12];
    const float* beta1  = (const float*)d_in[13];
    const float* rm1    = (const float*)d_in[14];
    const float* rv1    = (const float*)d_in[15];
    const float* alpha2 = (const float*)d_in[16];
    const float* gamma2 = (const float*)d_in[17];
    const float* beta2  = (const float*)d_in[18];
    const float* rm2    = (const float*)d_in[19];
    const float* rv2    = (const float*)d_in[20];
    float* out = (float*)d_out;

    float *t, *qkv, *attn, *t1, *wqkvT, *wprojT, *w1T, *w2T;
    cudaGetSymbolAddress((void**)&t,      g_t);
    cudaGetSymbolAddress((void**)&qkv,    g_qkv);
    cudaGetSymbolAddress((void**)&attn,   g_attn);
    cudaGetSymbolAddress((void**)&t1,     g_t1);
    cudaGetSymbolAddress((void**)&wqkvT,  g_wqkvT);
    cudaGetSymbolAddress((void**)&wprojT, g_wprojT);
    cudaGetSymbolAddress((void**)&w1T,    g_w1T);
    cudaGetSymbolAddress((void**)&w2T,    g_w2T);

    const int GEMM_SMEM = 1024 + 4 * 16384;
    const int FFN_SMEM  = 1024 + 192 * 1024;
    cudaFuncSetAttribute(k_tgemm, cudaFuncAttributeMaxDynamicSharedMemorySize, GEMM_SMEM);
    cudaFuncSetAttribute(k_ffn,   cudaFuncAttributeMaxDynamicSharedMemorySize, FFN_SMEM);
    cudaFuncSetAttribute(k_attn,  cudaFuncAttributeMaxDynamicSharedMemorySize, 2 * NN * 32 * 4);

    dim3 tb(32, 8);
    k_wt<<<dim3(768 / 32, 256 / 32), tb>>>(W_qkv, wqkvT, 256, 768);
    k_wt<<<dim3(256 / 32, 256 / 32), tb>>>(W_proj, wprojT, 256, 256);
    k_wt<<<dim3(CMID / 32, 256 / 32), tb>>>(W1, w1T, 256, CMID);
    k_wt<<<dim3(256 / 32, CMID / 32), tb>>>(W2, w2T, CMID, 256);
    k_in_transpose<<<dim3(7, 8, BB), tb>>>(x, t);
    k_tgemm<<<dim3(768 / 128, MM / 128), 256, GEMM_SMEM>>>(t, wqkvT, b_qkv, qkv,
        MM, 768, 256, 0, nullptr, nullptr, nullptr, nullptr, nullptr, nullptr);
    k_attn<<<dim3(8, BB), 256, 2 * NN * 32 * 4>>>(qkv, attn);
    k_tgemm<<<dim3(256 / 128, MM / 128), 256, GEMM_SMEM>>>(attn, wprojT, b_proj, t1,
        MM, 256, 256, 1, t, gamma1, beta1, rm1, rv1, alpha1);
    k_ffn<<<MM / 128, 256, FFN_SMEM>>>(t1, w1T, b1, w2T, b2, sa_w, sa_b,
        gamma2, beta2, rm2, rv2, alpha2, out);
}

// round 7
// speedup vs baseline: 1.2050x; 1.2050x over previous
#include <cuda_runtime.h>
#include <cstdint>
#include <math.h>

#define BB 256
#define CC 256
#define NN 196
#define MM (BB*NN)        // 50176
#define CMID 2048
#define EPSL 1e-5f

#if defined(__CUDA_ARCH_FEAT_SM103_ALL) || defined(__CUDA_ARCH_FEAT_SM100_ALL) || defined(__CUDA_ARCH_FEAT_SM101_ALL)
#define TC_OK 1
#else
#define TC_OK 0
#endif

// ---------------- scratch (device globals) -----------------------------------
__device__ float g_t   [(size_t)MM*CC];
__device__ float g_qkv [(size_t)MM*3*CC];
__device__ float g_attn[(size_t)MM*CC];
__device__ float g_t1  [(size_t)MM*CC];
__device__ float g_h   [(size_t)MM*CMID];
__device__ float g_wqkvT[(size_t)3*CC*CC];   // [768,256]
__device__ float g_wprojT[(size_t)CC*CC];    // [256,256]
__device__ float g_w1T  [(size_t)CMID*CC];   // [2048,256]
__device__ float g_w2T  [(size_t)CC*CMID];   // [256,2048]

// ---------------- PTX helpers -------------------------------------------------
__device__ __forceinline__ uint32_t smem_u32(const void* p) {
    uint32_t a;
    asm("{ .reg .u64 t; cvta.to.shared.u64 t, %1; cvt.u32.u64 %0, t; }" : "=r"(a) : "l"(p));
    return a;
}

#define MBAR_INIT(addr, cnt) \
    asm volatile("mbarrier.init.shared.b64 [%0], %1;" :: "r"(addr), "r"(cnt) : "memory")

#define MBAR_WAIT(addr, parity) do {                                              \
    uint32_t _m = (addr); uint32_t _p = (parity); uint32_t _d;                    \
    asm volatile("{\n\t.reg .pred p;\n\t"                                         \
        "mbarrier.try_wait.parity.acquire.cta.shared::cta.b64 p, [%1], %2;\n\t"   \
        "selp.b32 %0, 1, 0, p;\n\t}" : "=r"(_d) : "r"(_m), "r"(_p) : "memory");   \
    if (!_d) {                                                                     \
        asm volatile("{\n\t.reg .pred P1;\n\t"                                     \
            "W_%=:\n\t"                                                            \
            "mbarrier.try_wait.parity.acquire.cta.shared::cta.b64 P1, [%0], %1, 0x989680;\n\t" \
            "@P1 bra.uni D_%=;\n\t"                                                \
            "bra.uni W_%=;\n\t"                                                    \
            "D_%=:\n\t}" :: "r"(_m), "r"(_p) : "memory");                          \
    } } while (0)

#if TC_OK
__device__ __forceinline__ void mma_tf32(uint32_t d, uint64_t ad, uint64_t bd,
                                         uint32_t idesc, bool acc) {
    uint32_t e = acc ? 1u : 0u;
    asm volatile(
        "{\n\t.reg .pred p;\n\tsetp.ne.u32 p, %5, 0;\n\t"
        "tcgen05.mma.cta_group::1.kind::tf32 [%0], %1, %2, %3, {%4, %4, %4, %4}, p;\n\t}"
        :: "r"(d), "l"(ad), "l"(bd), "r"(idesc), "r"(0u), "r"(e) : "memory");
}

#define LDTM_X32(r, addr)                                                         \
    asm volatile("tcgen05.ld.sync.aligned.32x32b.x32.b32 "                        \
        "{%0, %1, %2, %3, %4, %5, %6, %7, %8, %9, %10, %11, %12, %13, %14, %15, " \
        " %16, %17, %18, %19, %20, %21, %22, %23, %24, %25, %26, %27, %28, %29, %30, %31}, [%32];" \
        : "=r"((r)[0]), "=r"((r)[1]), "=r"((r)[2]), "=r"((r)[3]),                 \
          "=r"((r)[4]), "=r"((r)[5]), "=r"((r)[6]), "=r"((r)[7]),                 \
          "=r"((r)[8]), "=r"((r)[9]), "=r"((r)[10]), "=r"((r)[11]),               \
          "=r"((r)[12]), "=r"((r)[13]), "=r"((r)[14]), "=r"((r)[15]),             \
          "=r"((r)[16]), "=r"((r)[17]), "=r"((r)[18]), "=r"((r)[19]),             \
          "=r"((r)[20]), "=r"((r)[21]), "=r"((r)[22]), "=r"((r)[23]),             \
          "=r"((r)[24]), "=r"((r)[25]), "=r"((r)[26]), "=r"((r)[27]),             \
          "=r"((r)[28]), "=r"((r)[29]), "=r"((r)[30]), "=r"((r)[31])              \
        : "r"(addr))
#endif

static constexpr uint64_t DESC_BASE =
    (uint64_t(2) << 61) | (uint64_t(1) << 46) | (uint64_t(64) << 32) | (uint64_t(1) << 16);

// ---------------- transpose x [B][C][N] -> t [B*N][C] -------------------------
__global__ void k_in_transpose(const float* __restrict__ x, float* __restrict__ t) {
    __shared__ float tile[32][33];
    int b = blockIdx.z;
    int n0 = blockIdx.x * 32, c0 = blockIdx.y * 32;
    int tx = threadIdx.x, ty = threadIdx.y;
    const float* xb = x + (size_t)b * CC * NN;
    #pragma unroll
    for (int j = 0; j < 32; j += 8) {
        int c = c0 + ty + j, n = n0 + tx;
        if (n < NN) tile[ty + j][tx] = xb[(size_t)c * NN + n];
    }
    __syncthreads();
    #pragma unroll
    for (int j = 0; j < 32; j += 8) {
        int n = n0 + ty + j, c = c0 + tx;
        if (n < NN) t[((size_t)b * NN + n) * CC + c] = tile[tx][ty + j];
    }
}

// ---------------- weight transpose W[R,C] -> Wt[C,R] --------------------------
__global__ void k_wt(const float* __restrict__ W, float* __restrict__ Wt, int R, int C) {
    __shared__ float tile[32][33];
    int c0 = blockIdx.x * 32, r0 = blockIdx.y * 32;
    int tx = threadIdx.x, ty = threadIdx.y;
    #pragma unroll
    for (int j = 0; j < 32; j += 8)
        tile[ty + j][tx] = W[(size_t)(r0 + ty + j) * C + c0 + tx];
    __syncthreads();
    #pragma unroll
    for (int j = 0; j < 32; j += 8)
        Wt[(size_t)(c0 + ty + j) * R + r0 + tx] = tile[tx][ty + j];
}

// ---------------- tcgen05 tf32 GEMM, 128x256 tile: out = A @ Bt^T + epilogue --
// epi 0: +bias
// epi 1: +bias, y = res + v, repbn(y)               (row-major out)
// epi 2: +bias, SpatialSILU                         (row-major out)
// epi 3: +bias, y = res + v, repbn(y), out in [B,C,N] layout
__global__ __launch_bounds__(256, 2)
void k_tgemm(const float* __restrict__ A, const float* __restrict__ Bt,
             const float* __restrict__ bias, float* __restrict__ out,
             int M, int N, int K, int epi,
             const float* __restrict__ res,
             const float* __restrict__ gam, const float* __restrict__ bet,
             const float* __restrict__ rm,  const float* __restrict__ rv,
             const float* __restrict__ alpha,
             const float* __restrict__ saw, const float* __restrict__ sab)
{
#if TC_OK
    extern __shared__ char smem_raw[];
    __shared__ uint64_t s_mbar[2];
    __shared__ uint32_t s_tmem;

    uint32_t sb_raw = smem_u32(smem_raw);
    uint32_t tbase = (sb_raw + 1023u) & ~1023u;
    char* tptr = smem_raw + (tbase - sb_raw);

    int tid = threadIdx.x;
    int wid = tid >> 5, lid = tid & 31;
    int m0 = blockIdx.y * 128, n0 = blockIdx.x * 256;

    if (wid == 0)
        asm volatile("tcgen05.alloc.cta_group::1.sync.aligned.shared::cta.b32 [%0], %1;"
                     :: "r"(smem_u32(&s_tmem)), "r"(256) : "memory");
    if (tid == 0) {
        MBAR_INIT(smem_u32(&s_mbar[0]), 1);
        MBAR_INIT(smem_u32(&s_mbar[1]), 1);
    }
    __syncthreads();
    uint32_t tmem = s_tmem;
    if (wid == 0)
        asm volatile("tcgen05.relinquish_alloc_permit.cta_group::1.sync.aligned;");

    // idesc: D=f32, A=tf32, B=tf32, N=256, M=128
    const uint32_t IDESC = (1u << 4) | (2u << 7) | (2u << 10) | (32u << 17) | (8u << 24);
    const int KC = K >> 5;
    int ph0 = 0, ph1 = 0;

    int row_ = tid >> 3, c4_ = tid & 7;
    uint32_t bo0 = row_ * 128 + c4_ * 16;
    uint32_t sw0 = bo0 ^ ((bo0 >> 3) & 0x70);

    // stage s: A @ s*49152 (16KB), B @ s*49152+16384 (32KB)
    float4 avr[4], bvr[8];
    {
        const float* Ag = A + (size_t)m0 * K;
        const float* Bg = Bt + (size_t)n0 * K;
        #pragma unroll
        for (int i = 0; i < 4; i++)
            avr[i] = *(const float4*)(Ag + (size_t)(row_ + i * 32) * K + c4_ * 4);
        #pragma unroll
        for (int i = 0; i < 8; i++)
            bvr[i] = *(const float4*)(Bg + (size_t)(row_ + i * 32) * K + c4_ * 4);
    }

    for (int kc = 0; kc < KC; kc++) {
        int buf = kc & 1;
        uint32_t mb = smem_u32(&s_mbar[buf]);
        if (kc >= 2) {
            if (buf == 0) { MBAR_WAIT(mb, ph0); ph0 ^= 1; }
            else          { MBAR_WAIT(mb, ph1); ph1 ^= 1; }
        }
        char* tA = tptr + buf * 49152;
        char* tB = tA + 16384;
        #pragma unroll
        for (int i = 0; i < 4; i++)
            *(float4*)(tA + sw0 + i * 4096) = avr[i];
        #pragma unroll
        for (int i = 0; i < 8; i++)
            *(float4*)(tB + sw0 + i * 4096) = bvr[i];
        asm volatile("fence.proxy.async.shared::cta;" ::: "memory");
        __syncthreads();
        if (tid == 0) {
            uint32_t sA = tbase + buf * 49152;
            uint32_t sB = sA + 16384;
            uint64_t ad = DESC_BASE | ((uint64_t)(sA >> 4) & 0x3FFF);
            uint64_t bd = DESC_BASE | ((uint64_t)(sB >> 4) & 0x3FFF);
            #pragma unroll
            for (int s = 0; s < 4; s++)
                mma_tf32(tmem, ad + s * 2, bd + s * 2, IDESC, (kc > 0) || (s > 0));
            asm volatile(
                "tcgen05.commit.cta_group::1.mbarrier::arrive::one.shared::cluster.b64 [%0];"
                :: "r"(mb) : "memory");
        }
        if (kc + 1 < KC) {
            const float* Ag = A + (size_t)m0 * K + (kc + 1) * 32;
            const float* Bg = Bt + (size_t)n0 * K + (kc + 1) * 32;
            #pragma unroll
            for (int i = 0; i < 4; i++)
                avr[i] = *(const float4*)(Ag + (size_t)(row_ + i * 32) * K + c4_ * 4);
            #pragma unroll
            for (int i = 0; i < 8; i++)
                bvr[i] = *(const float4*)(Bg + (size_t)(row_ + i * 32) * K + c4_ * 4);
        }
    }

    {
        int lb = (KC - 1) & 1;
        uint32_t mb = smem_u32(&s_mbar[lb]);
        if (lb == 0) { MBAR_WAIT(mb, ph0); }
        else         { MBAR_WAIT(mb, ph1); }
    }
    asm volatile("tcgen05.fence::after_thread_sync;" ::: "memory");
    __syncthreads();

    // ---- coalesced epilogue: 32x32 TMEM block -> smem transpose -> float4 IO --
    if (wid < 4) {
        float* spatch = (float*)tptr + wid * (32 * 33);
        int mrow = m0 + wid * 32;
        float alphav = (epi == 1 || epi == 3) ? alpha[0] : 0.f;
        int m_out = mrow + lid;
        int b_o = m_out / NN, nsp = m_out % NN;
        size_t obase = (size_t)b_o * CC * NN + nsp;
        for (int c0 = 0; c0 < 256; c0 += 32) {
            uint32_t r[32];
            LDTM_X32(r, tmem + c0);
            asm volatile("tcgen05.wait::ld.sync.aligned;" ::: "memory");
            #pragma unroll
            for (int j = 0; j < 32; j++) spatch[lid * 33 + j] = __uint_as_float(r[j]);
            __syncwarp();
            #pragma unroll
            for (int i = 0; i < 8; i++) {
                int rr = i * 4 + (lid >> 3);
                int c4 = (lid & 7) * 4;
                int m = mrow + rr;
                int n = n0 + c0 + c4;
                float vv[4];
                #pragma unroll
                for (int e = 0; e < 4; e++) vv[e] = spatch[rr * 33 + c4 + e];
                float4 bb = *(const float4*)(bias + n);
                vv[0] += bb.x; vv[1] += bb.y; vv[2] += bb.z; vv[3] += bb.w;
                if (epi == 1 || epi == 3) {
                    float4 r4 = *(const float4*)(res + (size_t)m * N + n);
                    float4 g4 = *(const float4*)(gam + n);
                    float4 b4 = *(const float4*)(bet + n);
                    float4 u4 = *(const float4*)(rm + n);
                    float4 s4 = *(const float4*)(rv + n);
                    float y;
                    y = r4.x + vv[0]; vv[0] = (y - u4.x) * (g4.x * rsqrtf(s4.x + EPSL)) + b4.x + alphav * y;
                    y = r4.y + vv[1]; vv[1] = (y - u4.y) * (g4.y * rsqrtf(s4.y + EPSL)) + b4.y + alphav * y;
                    y = r4.z + vv[2]; vv[2] = (y - u4.z) * (g4.z * rsqrtf(s4.z + EPSL)) + b4.z + alphav * y;
                    y = r4.w + vv[3]; vv[3] = (y - u4.w) * (g4.w * rsqrtf(s4.w + EPSL)) + b4.w + alphav * y;
                } else if (epi == 2) {
                    int bidx = m / NN;
                    float sw_ = saw[bidx], sbv = sab[bidx];
                    #pragma unroll
                    for (int e = 0; e < 4; e++) {
                        float w = sw_ * vv[e] + sbv;
                        vv[e] = vv[e] / (1.f + __expf(-w * vv[e]));
                    }
                }
                if (epi == 3) {
                    #pragma unroll
                    for (int e = 0; e < 4; e++) spatch[rr * 33 + c4 + e] = vv[e];
                } else {
                    *(float4*)(out + (size_t)m * N + n) = make_float4(vv[0], vv[1], vv[2], vv[3]);
                }
            }
            __syncwarp();
            if (epi == 3) {
                #pragma unroll
                for (int cc = 0; cc < 32; cc++)
                    out[obase + (size_t)(n0 + c0 + cc) * NN] = spatch[lid * 33 + cc];
                __syncwarp();
            }
        }
    }
    __syncthreads();
    if (tid == 0) {
        asm volatile("mbarrier.inval.shared.b64 [%0];" :: "r"(smem_u32(&s_mbar[0])) : "memory");
        asm volatile("mbarrier.inval.shared.b64 [%0];" :: "r"(smem_u32(&s_mbar[1])) : "memory");
    }
    __syncthreads();
    if (wid == 0)
        asm volatile("tcgen05.dealloc.cta_group::1.sync.aligned.b32 %0, %1;"
                     :: "r"(tmem), "r"(256));
#endif
}

// ---------------- attention: one block per (head, batch) ----------------------
__global__ void k_attn(const float* __restrict__ qkv, float* __restrict__ attnout) {
    extern __shared__ float sh[];
    float4* Ks = (float4*)sh;
    float4* Vs = (float4*)(sh + NN * 32);
    int h = blockIdx.x, b = blockIdx.y;
    int tid = threadIdx.x;
    size_t base = (size_t)b * NN * 768;
    int koff = 256 + h * 32, voff = 512 + h * 32;
    for (int i = tid; i < NN * 8; i += 256) {
        int m = i >> 3, d = i & 7;
        Ks[i] = *(const float4*)(qkv + base + (size_t)m * 768 + koff + d * 4);
        Vs[i] = *(const float4*)(qkv + base + (size_t)m * 768 + voff + d * 4);
    }
    __syncthreads();
    if (tid < NN) {
        float4 q4[8], o4[8];
        const float* qp = qkv + base + (size_t)tid * 768 + h * 32;
        #pragma unroll
        for (int i = 0; i < 8; i++) {
            float4 qv = *(const float4*)(qp + i * 4);
            const float sc = 0.17677669529663687f;
            q4[i] = make_float4(qv.x * sc, qv.y * sc, qv.z * sc, qv.w * sc);
            o4[i] = make_float4(0.f, 0.f, 0.f, 0.f);
        }
        float mx = -1e30f, l = 0.f;
        for (int m = 0; m < NN; m += 2) {
            const float4* k0 = Ks + m * 8;
            const float4* k1 = k0 + 8;
            float s0 = 0.f, s1 = 0.f;
            #pragma unroll
            for (int i = 0; i < 8; i++) {
                float4 a = q4[i], x0 = k0[i], x1 = k1[i];
                s0 += a.x * x0.x + a.y * x0.y + a.z * x0.z + a.w * x0.w;
                s1 += a.x * x1.x + a.y * x1.y + a.z * x1.z + a.w * x1.w;
            }
            float nm = fmaxf(mx, fmaxf(s0, s1));
            float f  = __expf(mx - nm);
            float p0 = __expf(s0 - nm);
            float p1 = __expf(s1 - nm);
            l = l * f + p0 + p1;
            const float4* v0 = Vs + m * 8;
            const float4* v1 = v0 + 8;
            #pragma unroll
            for (int i = 0; i < 8; i++) {
                float4 o = o4[i], a = v0[i], c = v1[i];
                o.x = o.x * f + p0 * a.x + p1 * c.x;
                o.y = o.y * f + p0 * a.y + p1 * c.y;
                o.z = o.z * f + p0 * a.z + p1 * c.z;
                o.w = o.w * f + p0 * a.w + p1 * c.w;
                o4[i] = o;
            }
            mx = nm;
        }
        float inv = 1.f / l;
        float* op = attnout + ((size_t)(b * NN + tid)) * CC + h * 32;
        #pragma unroll
        for (int i = 0; i < 8; i++) {
            float4 o = o4[i];
            *(float4*)(op + i * 4) = make_float4(o.x * inv, o.y * inv, o.z * inv, o.w * inv);
        }
    }
}

// ---------------- launch ------------------------------------------------------
extern "C" void kernel_launch(void* const* d_in, const int* in_sizes, int n_in,
                              void* d_out, int out_size) {
    const float* x      = (const float*)d_in[0];
    const float* W_qkv  = (const float*)d_in[1];
    const float* b_qkv  = (const float*)d_in[2];
    const float* W_proj = (const float*)d_in[3];
    const float* b_proj = (const float*)d_in[4];
    const float* W1     = (const float*)d_in[5];
    const float* b1     = (const float*)d_in[6];
    const float* W2     = (const float*)d_in[7];
    const float* b2     = (const float*)d_in[8];
    const float* sa_w   = (const float*)d_in[9];
    const float* sa_b   = (const float*)d_in[10];
    const float* alpha1 = (const float*)d_in[11];
    const float* gamma1 = (const float*)d_in[12];
    const float* beta1  = (const float*)d_in[13];
    const float* rm1    = (const float*)d_in[14];
    const float* rv1    = (const float*)d_in[15];
    const float* alpha2 = (const float*)d_in[16];
    const float* gamma2 = (const float*)d_in[17];
    const float* beta2  = (const float*)d_in[18];
    const float* rm2    = (const float*)d_in[19];
    const float* rv2    = (const float*)d_in[20];
    float* out = (float*)d_out;

    float *t, *qkv, *attn, *t1, *hbuf, *wqkvT, *wprojT, *w1T, *w2T;
    cudaGetSymbolAddress((void**)&t,      g_t);
    cudaGetSymbolAddress((void**)&qkv,    g_qkv);
    cudaGetSymbolAddress((void**)&attn,   g_attn);
    cudaGetSymbolAddress((void**)&t1,     g_t1);
    cudaGetSymbolAddress((void**)&hbuf,   g_h);
    cudaGetSymbolAddress((void**)&wqkvT,  g_wqkvT);
    cudaGetSymbolAddress((void**)&wprojT, g_wprojT);
    cudaGetSymbolAddress((void**)&w1T,    g_w1T);
    cudaGetSymbolAddress((void**)&w2T,    g_w2T);

    const int GEMM_SMEM = 1024 + 2 * 49152;   // 99328
    cudaFuncSetAttribute(k_tgemm, cudaFuncAttributeMaxDynamicSharedMemorySize, GEMM_SMEM);
    cudaFuncSetAttribute(k_attn,  cudaFuncAttributeMaxDynamicSharedMemorySize, 2 * NN * 32 * 4);

    dim3 tb(32, 8);
    k_wt<<<dim3(768 / 32, 256 / 32), tb>>>(W_qkv, wqkvT, 256, 768);
    k_wt<<<dim3(256 / 32, 256 / 32), tb>>>(W_proj, wprojT, 256, 256);
    k_wt<<<dim3(CMID / 32, 256 / 32), tb>>>(W1, w1T, 256, CMID);
    k_wt<<<dim3(256 / 32, CMID / 32), tb>>>(W2, w2T, CMID, 256);
    k_in_transpose<<<dim3(7, 8, BB), tb>>>(x, t);
    // QKV: [50176,256]@[256,768], 3 n-tiles
    k_tgemm<<<dim3(3, MM / 128), 256, GEMM_SMEM>>>(t, wqkvT, b_qkv, qkv,
        MM, 768, 256, 0, nullptr, nullptr, nullptr, nullptr, nullptr, nullptr, nullptr, nullptr);
    k_attn<<<dim3(8, BB), 256, 2 * NN * 32 * 4>>>(qkv, attn);
    // proj + residual + repbn1
    k_tgemm<<<dim3(1, MM / 128), 256, GEMM_SMEM>>>(attn, wprojT, b_proj, t1,
        MM, 256, 256, 1, t, gamma1, beta1, rm1, rv1, alpha1, nullptr, nullptr);
    // FFN1 + SpatialSILU, 8 n-tiles
    k_tgemm<<<dim3(8, MM / 128), 256, GEMM_SMEM>>>(t1, w1T, b1, hbuf,
        MM, CMID, 256, 2, nullptr, nullptr, nullptr, nullptr, nullptr, nullptr, sa_w, sa_b);
    // FFN2 + residual + repbn2, direct [B,C,N] output
    k_tgemm<<<dim3(1, MM / 128), 256, GEMM_SMEM>>>(hbuf, w2T, b2, out,
        MM, 256, CMID, 3, t1, gamma2, beta2, rm2, rv2, alpha2, nullptr, nullptr);
}

// round 8
// speedup vs baseline: 1.3554x; 1.1248x over previous
#include <cuda_runtime.h>
#include <cstdint>
#include <math.h>

#define BB 256
#define CC 256
#define NN 196
#define MM (BB*NN)        // 50176
#define CMID 2048
#define EPSL 1e-5f

#if defined(__CUDA_ARCH_FEAT_SM103_ALL) || defined(__CUDA_ARCH_FEAT_SM100_ALL) || defined(__CUDA_ARCH_FEAT_SM101_ALL)
#define TC_OK 1
#else
#define TC_OK 0
#endif

// ---------------- scratch (device globals) -----------------------------------
__device__ float g_t   [(size_t)MM*CC];
__device__ float g_qkv [(size_t)MM*3*CC];
__device__ float g_attn[(size_t)MM*CC];
__device__ float g_t1  [(size_t)MM*CC];
__device__ float g_h   [(size_t)MM*CMID];
__device__ float g_wqkvT[(size_t)3*CC*CC];   // [768,256]
__device__ float g_wprojT[(size_t)CC*CC];    // [256,256]
__device__ float g_w1T  [(size_t)CMID*CC];   // [2048,256]
__device__ float g_w2T  [(size_t)CC*CMID];   // [256,2048]

// ---------------- PTX helpers -------------------------------------------------
__device__ __forceinline__ uint32_t smem_u32(const void* p) {
    uint32_t a;
    asm("{ .reg .u64 t; cvta.to.shared.u64 t, %1; cvt.u32.u64 %0, t; }" : "=r"(a) : "l"(p));
    return a;
}

#define MBAR_INIT(addr, cnt) \
    asm volatile("mbarrier.init.shared.b64 [%0], %1;" :: "r"(addr), "r"(cnt) : "memory")

#define MBAR_WAIT(addr, parity) do {                                              \
    uint32_t _m = (addr); uint32_t _p = (parity); uint32_t _d;                    \
    asm volatile("{\n\t.reg .pred p;\n\t"                                         \
        "mbarrier.try_wait.parity.acquire.cta.shared::cta.b64 p, [%1], %2;\n\t"   \
        "selp.b32 %0, 1, 0, p;\n\t}" : "=r"(_d) : "r"(_m), "r"(_p) : "memory");   \
    if (!_d) {                                                                     \
        asm volatile("{\n\t.reg .pred P1;\n\t"                                     \
            "W_%=:\n\t"                                                            \
            "mbarrier.try_wait.parity.acquire.cta.shared::cta.b64 P1, [%0], %1, 0x989680;\n\t" \
            "@P1 bra.uni D_%=;\n\t"                                                \
            "bra.uni W_%=;\n\t"                                                    \
            "D_%=:\n\t}" :: "r"(_m), "r"(_p) : "memory");                          \
    } } while (0)

#if TC_OK
__device__ __forceinline__ void mma_tf32(uint32_t d, uint64_t ad, uint64_t bd,
                                         uint32_t idesc, bool acc) {
    uint32_t e = acc ? 1u : 0u;
    asm volatile(
        "{\n\t.reg .pred p;\n\tsetp.ne.u32 p, %5, 0;\n\t"
        "tcgen05.mma.cta_group::1.kind::tf32 [%0], %1, %2, %3, {%4, %4, %4, %4}, p;\n\t}"
        :: "r"(d), "l"(ad), "l"(bd), "r"(idesc), "r"(0u), "r"(e) : "memory");
}

#define LDTM_X32(r, addr)                                                         \
    asm volatile("tcgen05.ld.sync.aligned.32x32b.x32.b32 "                        \
        "{%0, %1, %2, %3, %4, %5, %6, %7, %8, %9, %10, %11, %12, %13, %14, %15, " \
        " %16, %17, %18, %19, %20, %21, %22, %23, %24, %25, %26, %27, %28, %29, %30, %31}, [%32];" \
        : "=r"((r)[0]), "=r"((r)[1]), "=r"((r)[2]), "=r"((r)[3]),                 \
          "=r"((r)[4]), "=r"((r)[5]), "=r"((r)[6]), "=r"((r)[7]),                 \
          "=r"((r)[8]), "=r"((r)[9]), "=r"((r)[10]), "=r"((r)[11]),               \
          "=r"((r)[12]), "=r"((r)[13]), "=r"((r)[14]), "=r"((r)[15]),             \
          "=r"((r)[16]), "=r"((r)[17]), "=r"((r)[18]), "=r"((r)[19]),             \
          "=r"((r)[20]), "=r"((r)[21]), "=r"((r)[22]), "=r"((r)[23]),             \
          "=r"((r)[24]), "=r"((r)[25]), "=r"((r)[26]), "=r"((r)[27]),             \
          "=r"((r)[28]), "=r"((r)[29]), "=r"((r)[30]), "=r"((r)[31])              \
        : "r"(addr))
#endif

static constexpr uint64_t DESC_BASE =
    (uint64_t(2) << 61) | (uint64_t(1) << 46) | (uint64_t(64) << 32) | (uint64_t(1) << 16);

// ---------------- transpose x [B][C][N] -> t [B*N][C] -------------------------
__global__ void k_in_transpose(const float* __restrict__ x, float* __restrict__ t) {
    __shared__ float tile[32][33];
    int b = blockIdx.z;
    int n0 = blockIdx.x * 32, c0 = blockIdx.y * 32;
    int tx = threadIdx.x, ty = threadIdx.y;
    const float* xb = x + (size_t)b * CC * NN;
    #pragma unroll
    for (int j = 0; j < 32; j += 8) {
        int c = c0 + ty + j, n = n0 + tx;
        if (n < NN) tile[ty + j][tx] = xb[(size_t)c * NN + n];
    }
    __syncthreads();
    #pragma unroll
    for (int j = 0; j < 32; j += 8) {
        int n = n0 + ty + j, c = c0 + tx;
        if (n < NN) t[((size_t)b * NN + n) * CC + c] = tile[tx][ty + j];
    }
}

// ---------------- weight transpose W[R,C] -> Wt[C,R] --------------------------
__global__ void k_wt(const float* __restrict__ W, float* __restrict__ Wt, int R, int C) {
    __shared__ float tile[32][33];
    int c0 = blockIdx.x * 32, r0 = blockIdx.y * 32;
    int tx = threadIdx.x, ty = threadIdx.y;
    #pragma unroll
    for (int j = 0; j < 32; j += 8)
        tile[ty + j][tx] = W[(size_t)(r0 + ty + j) * C + c0 + tx];
    __syncthreads();
    #pragma unroll
    for (int j = 0; j < 32; j += 8)
        Wt[(size_t)(c0 + ty + j) * R + r0 + tx] = tile[tx][ty + j];
}

// ---------------- tcgen05 tf32 GEMM 128x128 (R5): out = A @ Bt^T + epilogue ---
// epi 0: +bias ; epi 1: +bias, repbn(res+v) ; epi 2: +bias, SpatialSILU
__global__ __launch_bounds__(256)
void k_tgemm(const float* __restrict__ A, const float* __restrict__ Bt,
             const float* __restrict__ bias, float* __restrict__ out,
             int M, int N, int K, int epi,
             const float* __restrict__ res,
             const float* __restrict__ gam, const float* __restrict__ bet,
             const float* __restrict__ rm,  const float* __restrict__ rv,
             const float* __restrict__ alpha,
             const float* __restrict__ saw, const float* __restrict__ sab)
{
#if TC_OK
    extern __shared__ char smem_raw[];
    __shared__ uint64_t s_mbar[2];
    __shared__ uint32_t s_tmem;

    uint32_t sb_raw = smem_u32(smem_raw);
    uint32_t tbase = (sb_raw + 1023u) & ~1023u;
    char* tptr = smem_raw + (tbase - sb_raw);

    int tid = threadIdx.x;
    int wid = tid >> 5, lid = tid & 31;
    int m0 = blockIdx.y * 128, n0 = blockIdx.x * 128;

    if (wid == 0)
        asm volatile("tcgen05.alloc.cta_group::1.sync.aligned.shared::cta.b32 [%0], %1;"
                     :: "r"(smem_u32(&s_tmem)), "r"(128) : "memory");
    if (tid == 0) {
        MBAR_INIT(smem_u32(&s_mbar[0]), 1);
        MBAR_INIT(smem_u32(&s_mbar[1]), 1);
    }
    __syncthreads();
    uint32_t tmem = s_tmem;
    if (wid == 0)
        asm volatile("tcgen05.relinquish_alloc_permit.cta_group::1.sync.aligned;");

    const uint32_t IDESC = (1u << 4) | (2u << 7) | (2u << 10) | (16u << 17) | (8u << 24);
    const int KC = K >> 5;
    int ph0 = 0, ph1 = 0;

    int row_ = tid >> 3, c4_ = tid & 7;
    uint32_t bo0 = row_ * 128 + c4_ * 16;
    uint32_t sw0 = bo0 ^ ((bo0 >> 3) & 0x70);

    float4 avr[4], bvr[4];
    {
        const float* Ag = A + (size_t)m0 * K;
        const float* Bg = Bt + (size_t)n0 * K;
        #pragma unroll
        for (int i = 0; i < 4; i++) {
            int row = row_ + i * 32;
            avr[i] = *(const float4*)(Ag + (size_t)row * K + c4_ * 4);
            bvr[i] = *(const float4*)(Bg + (size_t)row * K + c4_ * 4);
        }
    }

    for (int kc = 0; kc < KC; kc++) {
        int buf = kc & 1;
        uint32_t mb = smem_u32(&s_mbar[buf]);
        if (kc >= 2) {
            if (buf == 0) { MBAR_WAIT(mb, ph0); ph0 ^= 1; }
            else          { MBAR_WAIT(mb, ph1); ph1 ^= 1; }
        }
        char* tA = tptr + buf * 32768;
        char* tB = tA + 16384;
        #pragma unroll
        for (int i = 0; i < 4; i++) {
            uint32_t sw = sw0 + i * 4096;
            *(float4*)(tA + sw) = avr[i];
            *(float4*)(tB + sw) = bvr[i];
        }
        asm volatile("fence.proxy.async.shared::cta;" ::: "memory");
        __syncthreads();
        if (tid == 0) {
            uint32_t sA = tbase + buf * 32768;
            uint32_t sB = sA + 16384;
            uint64_t ad = DESC_BASE | ((uint64_t)(sA >> 4) & 0x3FFF);
            uint64_t bd = DESC_BASE | ((uint64_t)(sB >> 4) & 0x3FFF);
            #pragma unroll
            for (int s = 0; s < 4; s++)
                mma_tf32(tmem, ad + s * 2, bd + s * 2, IDESC, (kc > 0) || (s > 0));
            asm volatile(
                "tcgen05.commit.cta_group::1.mbarrier::arrive::one.shared::cluster.b64 [%0];"
                :: "r"(mb) : "memory");
        }
        if (kc + 1 < KC) {
            const float* Ag = A + (size_t)m0 * K + (kc + 1) * 32;
            const float* Bg = Bt + (size_t)n0 * K + (kc + 1) * 32;
            #pragma unroll
            for (int i = 0; i < 4; i++) {
                int row = row_ + i * 32;
                avr[i] = *(const float4*)(Ag + (size_t)row * K + c4_ * 4);
                bvr[i] = *(const float4*)(Bg + (size_t)row * K + c4_ * 4);
            }
        }
    }

    {
        int lb = (KC - 1) & 1;
        uint32_t mb = smem_u32(&s_mbar[lb]);
        if (lb == 0) { MBAR_WAIT(mb, ph0); }
        else         { MBAR_WAIT(mb, ph1); }
    }
    asm volatile("tcgen05.fence::after_thread_sync;" ::: "memory");
    __syncthreads();

    if (wid < 4) {
        float* spatch = (float*)tptr + wid * (32 * 33);
        int mrow = m0 + wid * 32;
        float alphav = (epi == 1) ? alpha[0] : 0.f;
        for (int c0 = 0; c0 < 128; c0 += 32) {
            uint32_t r[32];
            LDTM_X32(r, tmem + c0);
            asm volatile("tcgen05.wait::ld.sync.aligned;" ::: "memory");
            #pragma unroll
            for (int j = 0; j < 32; j++) spatch[lid * 33 + j] = __uint_as_float(r[j]);
            __syncwarp();
            #pragma unroll
            for (int i = 0; i < 8; i++) {
                int rr = i * 4 + (lid >> 3);
                int c4 = (lid & 7) * 4;
                int m = mrow + rr;
                int n = n0 + c0 + c4;
                float vv[4];
                #pragma unroll
                for (int e = 0; e < 4; e++) vv[e] = spatch[rr * 33 + c4 + e];
                float4 bb = *(const float4*)(bias + n);
                vv[0] += bb.x; vv[1] += bb.y; vv[2] += bb.z; vv[3] += bb.w;
                if (epi == 1) {
                    float4 r4 = *(const float4*)(res + (size_t)m * N + n);
                    float4 g4 = *(const float4*)(gam + n);
                    float4 b4 = *(const float4*)(bet + n);
                    float4 u4 = *(const float4*)(rm + n);
                    float4 s4 = *(const float4*)(rv + n);
                    float y;
                    y = r4.x + vv[0]; vv[0] = (y - u4.x) * (g4.x * rsqrtf(s4.x + EPSL)) + b4.x + alphav * y;
                    y = r4.y + vv[1]; vv[1] = (y - u4.y) * (g4.y * rsqrtf(s4.y + EPSL)) + b4.y + alphav * y;
                    y = r4.z + vv[2]; vv[2] = (y - u4.z) * (g4.z * rsqrtf(s4.z + EPSL)) + b4.z + alphav * y;
                    y = r4.w + vv[3]; vv[3] = (y - u4.w) * (g4.w * rsqrtf(s4.w + EPSL)) + b4.w + alphav * y;
                } else if (epi == 2) {
                    int bidx = m / NN;
                    float sw_ = saw[bidx], sbv = sab[bidx];
                    #pragma unroll
                    for (int e = 0; e < 4; e++) {
                        float w = sw_ * vv[e] + sbv;
                        vv[e] = vv[e] / (1.f + __expf(-w * vv[e]));
                    }
                }
                *(float4*)(out + (size_t)m * N + n) = make_float4(vv[0], vv[1], vv[2], vv[3]);
            }
            __syncwarp();
        }
    }
    __syncthreads();
    if (tid == 0) {
        asm volatile("mbarrier.inval.shared.b64 [%0];" :: "r"(smem_u32(&s_mbar[0])) : "memory");
        asm volatile("mbarrier.inval.shared.b64 [%0];" :: "r"(smem_u32(&s_mbar[1])) : "memory");
    }
    __syncthreads();
    if (wid == 0)
        asm volatile("tcgen05.dealloc.cta_group::1.sync.aligned.b32 %0, %1;"
                     :: "r"(tmem), "r"(128));
#endif
}

// ---------------- wide GEMM 128x256 for FFN2: single read of hbuf, BCN output -
__global__ __launch_bounds__(256)
void k_tgemm_w(const float* __restrict__ A, const float* __restrict__ Bt,
               const float* __restrict__ bias, float* __restrict__ out,
               int K,
               const float* __restrict__ res,
               const float* __restrict__ gam, const float* __restrict__ bet,
               const float* __restrict__ rm,  const float* __restrict__ rv,
               const float* __restrict__ alpha)
{
#if TC_OK
    extern __shared__ char smem_raw[];
    __shared__ uint64_t s_mbar[2];
    __shared__ uint32_t s_tmem;

    uint32_t sb_raw = smem_u32(smem_raw);
    uint32_t tbase = (sb_raw + 1023u) & ~1023u;
    char* tptr = smem_raw + (tbase - sb_raw);

    int tid = threadIdx.x;
    int wid = tid >> 5, lid = tid & 31;
    int m0 = blockIdx.x * 128;
    const int N = 256;

    if (wid == 0)
        asm volatile("tcgen05.alloc.cta_group::1.sync.aligned.shared::cta.b32 [%0], %1;"
                     :: "r"(smem_u32(&s_tmem)), "r"(256) : "memory");
    if (tid == 0) {
        MBAR_INIT(smem_u32(&s_mbar[0]), 1);
        MBAR_INIT(smem_u32(&s_mbar[1]), 1);
    }
    __syncthreads();
    uint32_t tmem = s_tmem;
    if (wid == 0)
        asm volatile("tcgen05.relinquish_alloc_permit.cta_group::1.sync.aligned;");

    const uint32_t IDESC = (1u << 4) | (2u << 7) | (2u << 10) | (32u << 17) | (8u << 24);
    const int KC = K >> 5;
    int ph0 = 0, ph1 = 0;

    int row_ = tid >> 3, c4_ = tid & 7;
    uint32_t bo0 = row_ * 128 + c4_ * 16;
    uint32_t sw0 = bo0 ^ ((bo0 >> 3) & 0x70);

    float4 avr[4], bvr[8];
    {
        const float* Ag = A + (size_t)m0 * K;
        #pragma unroll
        for (int i = 0; i < 4; i++)
            avr[i] = *(const float4*)(Ag + (size_t)(row_ + i * 32) * K + c4_ * 4);
        #pragma unroll
        for (int i = 0; i < 8; i++)
            bvr[i] = *(const float4*)(Bt + (size_t)(row_ + i * 32) * K + c4_ * 4);
    }

    for (int kc = 0; kc < KC; kc++) {
        int buf = kc & 1;
        uint32_t mb = smem_u32(&s_mbar[buf]);
        if (kc >= 2) {
            if (buf == 0) { MBAR_WAIT(mb, ph0); ph0 ^= 1; }
            else          { MBAR_WAIT(mb, ph1); ph1 ^= 1; }
        }
        char* tA = tptr + buf * 49152;
        char* tB = tA + 16384;
        #pragma unroll
        for (int i = 0; i < 4; i++)
            *(float4*)(tA + sw0 + i * 4096) = avr[i];
        #pragma unroll
        for (int i = 0; i < 8; i++)
            *(float4*)(tB + sw0 + i * 4096) = bvr[i];
        asm volatile("fence.proxy.async.shared::cta;" ::: "memory");
        __syncthreads();
        if (tid == 0) {
            uint32_t sA = tbase + buf * 49152;
            uint32_t sB = sA + 16384;
            uint64_t ad = DESC_BASE | ((uint64_t)(sA >> 4) & 0x3FFF);
            uint64_t bd = DESC_BASE | ((uint64_t)(sB >> 4) & 0x3FFF);
            #pragma unroll
            for (int s = 0; s < 4; s++)
                mma_tf32(tmem, ad + s * 2, bd + s * 2, IDESC, (kc > 0) || (s > 0));
            asm volatile(
                "tcgen05.commit.cta_group::1.mbarrier::arrive::one.shared::cluster.b64 [%0];"
                :: "r"(mb) : "memory");
        }
        if (kc + 1 < KC) {
            const float* Ag = A + (size_t)m0 * K + (kc + 1) * 32;
            const float* Bg = Bt + (kc + 1) * 32;
            #pragma unroll
            for (int i = 0; i < 4; i++)
                avr[i] = *(const float4*)(Ag + (size_t)(row_ + i * 32) * K + c4_ * 4);
            #pragma unroll
            for (int i = 0; i < 8; i++)
                bvr[i] = *(const float4*)(Bg + (size_t)(row_ + i * 32) * K + c4_ * 4);
        }
    }

    {
        int lb = (KC - 1) & 1;
        uint32_t mb = smem_u32(&s_mbar[lb]);
        if (lb == 0) { MBAR_WAIT(mb, ph0); }
        else         { MBAR_WAIT(mb, ph1); }
    }
    asm volatile("tcgen05.fence::after_thread_sync;" ::: "memory");
    __syncthreads();

    // epilogue: +bias, repbn(res+v), write [B,C,N]
    if (wid < 4) {
        float* spatch = (float*)tptr + wid * (32 * 33);
        int mrow = m0 + wid * 32;
        float alphav = alpha[0];
        int m_out = mrow + lid;
        int b_o = m_out / NN, nsp = m_out % NN;
        size_t obase = (size_t)b_o * CC * NN + nsp;
        for (int c0 = 0; c0 < 256; c0 += 32) {
            uint32_t r[32];
            LDTM_X32(r, tmem + c0);
            asm volatile("tcgen05.wait::ld.sync.aligned;" ::: "memory");
            #pragma unroll
            for (int j = 0; j < 32; j++) spatch[lid * 33 + j] = __uint_as_float(r[j]);
            __syncwarp();
            #pragma unroll
            for (int i = 0; i < 8; i++) {
                int rr = i * 4 + (lid >> 3);
                int c4 = (lid & 7) * 4;
                int m = mrow + rr;
                int n = c0 + c4;
                float vv[4];
                #pragma unroll
                for (int e = 0; e < 4; e++) vv[e] = spatch[rr * 33 + c4 + e];
                float4 bb = *(const float4*)(bias + n);
                float4 r4 = *(const float4*)(res + (size_t)m * N + n);
                float4 g4 = *(const float4*)(gam + n);
                float4 b4 = *(const float4*)(bet + n);
                float4 u4 = *(const float4*)(rm + n);
                float4 s4 = *(const float4*)(rv + n);
                float y;
                y = r4.x + vv[0] + bb.x; vv[0] = (y - u4.x) * (g4.x * rsqrtf(s4.x + EPSL)) + b4.x + alphav * y;
                y = r4.y + vv[1] + bb.y; vv[1] = (y - u4.y) * (g4.y * rsqrtf(s4.y + EPSL)) + b4.y + alphav * y;
                y = r4.z + vv[2] + bb.z; vv[2] = (y - u4.z) * (g4.z * rsqrtf(s4.z + EPSL)) + b4.z + alphav * y;
                y = r4.w + vv[3] + bb.w; vv[3] = (y - u4.w) * (g4.w * rsqrtf(s4.w + EPSL)) + b4.w + alphav * y;
                #pragma unroll
                for (int e = 0; e < 4; e++) spatch[rr * 33 + c4 + e] = vv[e];
            }
            __syncwarp();
            #pragma unroll
            for (int cc = 0; cc < 32; cc++)
                out[obase + (size_t)(c0 + cc) * NN] = spatch[lid * 33 + cc];
            __syncwarp();
        }
    }
    __syncthreads();
    if (tid == 0) {
        asm volatile("mbarrier.inval.shared.b64 [%0];" :: "r"(smem_u32(&s_mbar[0])) : "memory");
        asm volatile("mbarrier.inval.shared.b64 [%0];" :: "r"(smem_u32(&s_mbar[1])) : "memory");
    }
    __syncthreads();
    if (wid == 0)
        asm volatile("tcgen05.dealloc.cta_group::1.sync.aligned.b32 %0, %1;"
                     :: "r"(tmem), "r"(256));
#endif
}

// ---------------- attention: one block per (head, batch) ----------------------
__global__ void k_attn(const float* __restrict__ qkv, float* __restrict__ attnout) {
    extern __shared__ float sh[];
    float4* Ks = (float4*)sh;
    float4* Vs = (float4*)(sh + NN * 32);
    int h = blockIdx.x, b = blockIdx.y;
    int tid = threadIdx.x;
    size_t base = (size_t)b * NN * 768;
    int koff = 256 + h * 32, voff = 512 + h * 32;
    for (int i = tid; i < NN * 8; i += 256) {
        int m = i >> 3, d = i & 7;
        Ks[i] = *(const float4*)(qkv + base + (size_t)m * 768 + koff + d * 4);
        Vs[i] = *(const float4*)(qkv + base + (size_t)m * 768 + voff + d * 4);
    }
    __syncthreads();
    if (tid < NN) {
        float4 q4[8], o4[8];
        const float* qp = qkv + base + (size_t)tid * 768 + h * 32;
        #pragma unroll
        for (int i = 0; i < 8; i++) {
            float4 qv = *(const float4*)(qp + i * 4);
            const float sc = 0.17677669529663687f;
            q4[i] = make_float4(qv.x * sc, qv.y * sc, qv.z * sc, qv.w * sc);
            o4[i] = make_float4(0.f, 0.f, 0.f, 0.f);
        }
        float mx = -1e30f, l = 0.f;
        for (int m = 0; m < NN; m += 2) {
            const float4* k0 = Ks + m * 8;
            const float4* k1 = k0 + 8;
            float s0 = 0.f, s1 = 0.f;
            #pragma unroll
            for (int i = 0; i < 8; i++) {
                float4 a = q4[i], x0 = k0[i], x1 = k1[i];
                s0 += a.x * x0.x + a.y * x0.y + a.z * x0.z + a.w * x0.w;
                s1 += a.x * x1.x + a.y * x1.y + a.z * x1.z + a.w * x1.w;
            }
            float nm = fmaxf(mx, fmaxf(s0, s1));
            float f  = __expf(mx - nm);
            float p0 = __expf(s0 - nm);
            float p1 = __expf(s1 - nm);
            l = l * f + p0 + p1;
            const float4* v0 = Vs + m * 8;
            const float4* v1 = v0 + 8;
            #pragma unroll
            for (int i = 0; i < 8; i++) {
                float4 o = o4[i], a = v0[i], c = v1[i];
                o.x = o.x * f + p0 * a.x + p1 * c.x;
                o.y = o.y * f + p0 * a.y + p1 * c.y;
                o.z = o.z * f + p0 * a.z + p1 * c.z;
                o.w = o.w * f + p0 * a.w + p1 * c.w;
                o4[i] = o;
            }
            mx = nm;
        }
        float inv = 1.f / l;
        float* op = attnout + ((size_t)(b * NN + tid)) * CC + h * 32;
        #pragma unroll
        for (int i = 0; i < 8; i++) {
            float4 o = o4[i];
            *(float4*)(op + i * 4) = make_float4(o.x * inv, o.y * inv, o.z * inv, o.w * inv);
        }
    }
}

// ---------------- launch ------------------------------------------------------
extern "C" void kernel_launch(void* const* d_in, const int* in_sizes, int n_in,
                              void* d_out, int out_size) {
    const float* x      = (const float*)d_in[0];
    const float* W_qkv  = (const float*)d_in[1];
    const float* b_qkv  = (const float*)d_in[2];
    const float* W_proj = (const float*)d_in[3];
    const float* b_proj = (const float*)d_in[4];
    const float* W1     = (const float*)d_in[5];
    const float* b1     = (const float*)d_in[6];
    const float* W2     = (const float*)d_in[7];
    const float* b2     = (const float*)d_in[8];
    const float* sa_w   = (const float*)d_in[9];
    const float* sa_b   = (const float*)d_in[10];
    const float* alpha1 = (const float*)d_in[11];
    const float* gamma1 = (const float*)d_in[12];
    const float* beta1  = (const float*)d_in[13];
    const float* rm1    = (const float*)d_in[14];
    const float* rv1    = (const float*)d_in[15];
    const float* alpha2 = (const float*)d_in[16];
    const float* gamma2 = (const float*)d_in[17];
    const float* beta2  = (const float*)d_in[18];
    const float* rm2    = (const float*)d_in[19];
    const float* rv2    = (const float*)d_in[20];
    float* out = (float*)d_out;

    float *t, *qkv, *attn, *t1, *hbuf, *wqkvT, *wprojT, *w1T, *w2T;
    cudaGetSymbolAddress((void**)&t,      g_t);
    cudaGetSymbolAddress((void**)&qkv,    g_qkv);
    cudaGetSymbolAddress((void**)&attn,   g_attn);
    cudaGetSymbolAddress((void**)&t1,     g_t1);
    cudaGetSymbolAddress((void**)&hbuf,   g_h);
    cudaGetSymbolAddress((void**)&wqkvT,  g_wqkvT);
    cudaGetSymbolAddress((void**)&wprojT, g_wprojT);
    cudaGetSymbolAddress((void**)&w1T,    g_w1T);
    cudaGetSymbolAddress((void**)&w2T,    g_w2T);

    const int GEMM_SMEM  = 1024 + 4 * 16384;   // 66560 (128x128 kernel)
    const int GEMMW_SMEM = 1024 + 2 * 49152;   // 99328 (128x256 kernel)
    cudaFuncSetAttribute(k_tgemm,   cudaFuncAttributeMaxDynamicSharedMemorySize, GEMM_SMEM);
    cudaFuncSetAttribute(k_tgemm_w, cudaFuncAttributeMaxDynamicSharedMemorySize, GEMMW_SMEM);
    cudaFuncSetAttribute(k_attn,    cudaFuncAttributeMaxDynamicSharedMemorySize, 2 * NN * 32 * 4);

    dim3 tb(32, 8);
    k_wt<<<dim3(768 / 32, 256 / 32), tb>>>(W_qkv, wqkvT, 256, 768);
    k_wt<<<dim3(256 / 32, 256 / 32), tb>>>(W_proj, wprojT, 256, 256);
    k_wt<<<dim3(CMID / 32, 256 / 32), tb>>>(W1, w1T, 256, CMID);
    k_wt<<<dim3(256 / 32, CMID / 32), tb>>>(W2, w2T, CMID, 256);
    k_in_transpose<<<dim3(7, 8, BB), tb>>>(x, t);
    // QKV: [50176,256]@[256,768]
    k_tgemm<<<dim3(768 / 128, MM / 128), 256, GEMM_SMEM>>>(t, wqkvT, b_qkv, qkv,
        MM, 768, 256, 0, nullptr, nullptr, nullptr, nullptr, nullptr, nullptr, nullptr, nullptr);
    k_attn<<<dim3(8, BB), 256, 2 * NN * 32 * 4>>>(qkv, attn);
    // proj + residual + repbn1
    k_tgemm<<<dim3(256 / 128, MM / 128), 256, GEMM_SMEM>>>(attn, wprojT, b_proj, t1,
        MM, 256, 256, 1, t, gamma1, beta1, rm1, rv1, alpha1, nullptr, nullptr);
    // FFN1 + SpatialSILU
    k_tgemm<<<dim3(CMID / 128, MM / 128), 256, GEMM_SMEM>>>(t1, w1T, b1, hbuf,
        MM, CMID, 256, 2, nullptr, nullptr, nullptr, nullptr, nullptr, nullptr, sa_w, sa_b);
    // FFN2 (wide, single hbuf read) + residual + repbn2, direct [B,C,N] output
    k_tgemm_w<<<MM / 128, 256, GEMMW_SMEM>>>(hbuf, w2T, b2, out,
        CMID, t1, gamma2, beta2, rm2, rv2, alpha2);
}

// round 9
// speedup vs baseline: 1.6308x; 1.2032x over previous
#include <cuda_runtime.h>
#include <cuda.h>
#include <cstdint>
#include <math.h>

#define BB 256
#define CC 256
#define NN 196
#define MM (BB*NN)        // 50176
#define CMID 2048
#define EPSL 1e-5f

#if defined(__CUDA_ARCH_FEAT_SM103_ALL) || defined(__CUDA_ARCH_FEAT_SM100_ALL) || defined(__CUDA_ARCH_FEAT_SM101_ALL)
#define TC_OK 1
#else
#define TC_OK 0
#endif

// ---------------- scratch (device globals) -----------------------------------
__device__ float g_t   [(size_t)MM*CC];
__device__ float g_qkv [(size_t)MM*3*CC];
__device__ float g_attn[(size_t)MM*CC];
__device__ float g_t1  [(size_t)MM*CC];
__device__ float g_h   [(size_t)MM*CMID];
__device__ float g_wqkvT[(size_t)3*CC*CC];   // [768,256]
__device__ float g_wprojT[(size_t)CC*CC];    // [256,256]
__device__ float g_w1T  [(size_t)CMID*CC];   // [2048,256]
__device__ float g_w2T  [(size_t)CC*CMID];   // [256,2048]

// ---------------- PTX helpers -------------------------------------------------
__device__ __forceinline__ uint32_t smem_u32(const void* p) {
    uint32_t a;
    asm("{ .reg .u64 t; cvta.to.shared.u64 t, %1; cvt.u32.u64 %0, t; }" : "=r"(a) : "l"(p));
    return a;
}

#define MBAR_INIT(addr, cnt) \
    asm volatile("mbarrier.init.shared.b64 [%0], %1;" :: "r"(addr), "r"(cnt) : "memory")

#define MBAR_WAIT(addr, parity) do {                                              \
    uint32_t _m = (addr); uint32_t _p = (parity); uint32_t _d;                    \
    asm volatile("{\n\t.reg .pred p;\n\t"                                         \
        "mbarrier.try_wait.parity.acquire.cta.shared::cta.b64 p, [%1], %2;\n\t"   \
        "selp.b32 %0, 1, 0, p;\n\t}" : "=r"(_d) : "r"(_m), "r"(_p) : "memory");   \
    if (!_d) {                                                                     \
        asm volatile("{\n\t.reg .pred P1;\n\t"                                     \
            "W_%=:\n\t"                                                            \
            "mbarrier.try_wait.parity.acquire.cta.shared::cta.b64 P1, [%0], %1, 0x989680;\n\t" \
            "@P1 bra.uni D_%=;\n\t"                                                \
            "bra.uni W_%=;\n\t"                                                    \
            "D_%=:\n\t}" :: "r"(_m), "r"(_p) : "memory");                          \
    } } while (0)

#if TC_OK
#define MBAR_EXPECT(mbar, bytes) \
    asm volatile("mbarrier.arrive.expect_tx.shared.b64 _, [%0], %1;" \
                 :: "r"(mbar), "r"(bytes) : "memory")

#define TMA_LD2D(smem, tmapp, c0, c1, mbar) \
    asm volatile("cp.async.bulk.tensor.2d.shared::cta.global.tile.mbarrier::complete_tx::bytes " \
                 "[%0], [%1, {%2, %3}], [%4];" \
                 :: "r"(smem), "l"(tmapp), "r"(c0), "r"(c1), "r"(mbar) : "memory")

__device__ __forceinline__ void mma_tf32(uint32_t d, uint64_t ad, uint64_t bd,
                                         uint32_t idesc, bool acc) {
    uint32_t e = acc ? 1u : 0u;
    asm volatile(
        "{\n\t.reg .pred p;\n\tsetp.ne.u32 p, %5, 0;\n\t"
        "tcgen05.mma.cta_group::1.kind::tf32 [%0], %1, %2, %3, {%4, %4, %4, %4}, p;\n\t}"
        :: "r"(d), "l"(ad), "l"(bd), "r"(idesc), "r"(0u), "r"(e) : "memory");
}

#define LDTM_X32(r, addr)                                                         \
    asm volatile("tcgen05.ld.sync.aligned.32x32b.x32.b32 "                        \
        "{%0, %1, %2, %3, %4, %5, %6, %7, %8, %9, %10, %11, %12, %13, %14, %15, " \
        " %16, %17, %18, %19, %20, %21, %22, %23, %24, %25, %26, %27, %28, %29, %30, %31}, [%32];" \
        : "=r"((r)[0]), "=r"((r)[1]), "=r"((r)[2]), "=r"((r)[3]),                 \
          "=r"((r)[4]), "=r"((r)[5]), "=r"((r)[6]), "=r"((r)[7]),                 \
          "=r"((r)[8]), "=r"((r)[9]), "=r"((r)[10]), "=r"((r)[11]),               \
          "=r"((r)[12]), "=r"((r)[13]), "=r"((r)[14]), "=r"((r)[15]),             \
          "=r"((r)[16]), "=r"((r)[17]), "=r"((r)[18]), "=r"((r)[19]),             \
          "=r"((r)[20]), "=r"((r)[21]), "=r"((r)[22]), "=r"((r)[23]),             \
          "=r"((r)[24]), "=r"((r)[25]), "=r"((r)[26]), "=r"((r)[27]),             \
          "=r"((r)[28]), "=r"((r)[29]), "=r"((r)[30]), "=r"((r)[31])              \
        : "r"(addr))
#endif

static constexpr uint64_t DESC_BASE =
    (uint64_t(2) << 61) | (uint64_t(1) << 46) | (uint64_t(64) << 32) | (uint64_t(1) << 16);

// ---------------- transpose x [B][C][N] -> t [B*N][C] -------------------------
__global__ void k_in_transpose(const float* __restrict__ x, float* __restrict__ t) {
    __shared__ float tile[32][33];
    int b = blockIdx.z;
    int n0 = blockIdx.x * 32, c0 = blockIdx.y * 32;
    int tx = threadIdx.x, ty = threadIdx.y;
    const float* xb = x + (size_t)b * CC * NN;
    #pragma unroll
    for (int j = 0; j < 32; j += 8) {
        int c = c0 + ty + j, n = n0 + tx;
        if (n < NN) tile[ty + j][tx] = xb[(size_t)c * NN + n];
    }
    __syncthreads();
    #pragma unroll
    for (int j = 0; j < 32; j += 8) {
        int n = n0 + ty + j, c = c0 + tx;
        if (n < NN) t[((size_t)b * NN + n) * CC + c] = tile[tx][ty + j];
    }
}

// ---------------- weight transpose W[R,C] -> Wt[C,R] --------------------------
__global__ void k_wt(const float* __restrict__ W, float* __restrict__ Wt, int R, int C) {
    __shared__ float tile[32][33];
    int c0 = blockIdx.x * 32, r0 = blockIdx.y * 32;
    int tx = threadIdx.x, ty = threadIdx.y;
    #pragma unroll
    for (int j = 0; j < 32; j += 8)
        tile[ty + j][tx] = W[(size_t)(r0 + ty + j) * C + c0 + tx];
    __syncthreads();
    #pragma unroll
    for (int j = 0; j < 32; j += 8)
        Wt[(size_t)(c0 + ty + j) * R + r0 + tx] = tile[tx][ty + j];
}

// ---------------- TMA tcgen05 tf32 GEMM 128x128: out = A @ Bt^T + epilogue ----
// epi 0: +bias ; epi 1: +bias, repbn(res+v) ; epi 2: +bias, SpatialSILU
__global__ __launch_bounds__(256)
void k_tgemm(const __grid_constant__ CUtensorMap tmA,
             const __grid_constant__ CUtensorMap tmB,
             const float* __restrict__ bias, float* __restrict__ out,
             int N, int K, int epi,
             const float* __restrict__ res,
             const float* __restrict__ gam, const float* __restrict__ bet,
             const float* __restrict__ rm,  const float* __restrict__ rv,
             const float* __restrict__ alpha,
             const float* __restrict__ saw, const float* __restrict__ sab)
{
#if TC_OK
    extern __shared__ char smem_raw[];
    __shared__ uint64_t s_mbar[5];   // full0, full1, empty0, empty1, done
    __shared__ uint32_t s_tmem;

    uint32_t sb_raw = smem_u32(smem_raw);
    uint32_t tbase = (sb_raw + 1023u) & ~1023u;
    char* tptr = smem_raw + (tbase - sb_raw);

    int tid = threadIdx.x;
    int wid = tid >> 5, lid = tid & 31;
    int m0 = blockIdx.y * 128, n0 = blockIdx.x * 128;

    if (wid == 0)
        asm volatile("tcgen05.alloc.cta_group::1.sync.aligned.shared::cta.b32 [%0], %1;"
                     :: "r"(smem_u32(&s_tmem)), "r"(128) : "memory");
    if (tid == 0)
        for (int i = 0; i < 5; i++) MBAR_INIT(smem_u32(&s_mbar[i]), 1);
    __syncthreads();
    uint32_t tmem = s_tmem;
    if (wid == 0)
        asm volatile("tcgen05.relinquish_alloc_permit.cta_group::1.sync.aligned;");

    const uint32_t IDESC = (1u << 4) | (2u << 7) | (2u << 10) | (16u << 17) | (8u << 24);
    const int KC = K >> 5;

    if (tid == 0) {
        uint32_t full[2]  = { smem_u32(&s_mbar[0]), smem_u32(&s_mbar[1]) };
        uint32_t empty[2] = { smem_u32(&s_mbar[2]), smem_u32(&s_mbar[3]) };
        int phf[2] = {0, 0}, phe[2] = {0, 0};
        // prologue: stage 0, 1
        #pragma unroll
        for (int p = 0; p < 2; p++) {
            uint32_t sA = tbase + p * 32768, sB = sA + 16384;
            MBAR_EXPECT(full[p], 32768);
            TMA_LD2D(sA, &tmA, p * 32, m0, full[p]);
            TMA_LD2D(sB, &tmB, p * 32, n0, full[p]);
        }
        for (int kc = 0; kc < KC; kc++) {
            int buf = kc & 1;
            uint32_t sA = tbase + buf * 32768, sB = sA + 16384;
            MBAR_WAIT(full[buf], phf[buf]); phf[buf] ^= 1;
            uint64_t ad = DESC_BASE | ((uint64_t)(sA >> 4) & 0x3FFF);
            uint64_t bd = DESC_BASE | ((uint64_t)(sB >> 4) & 0x3FFF);
            #pragma unroll
            for (int s = 0; s < 4; s++)
                mma_tf32(tmem, ad + s * 2, bd + s * 2, IDESC, (kc > 0) || (s > 0));
            asm volatile(
                "tcgen05.commit.cta_group::1.mbarrier::arrive::one.shared::cluster.b64 [%0];"
                :: "r"(empty[buf]) : "memory");
            if (kc + 2 < KC) {
                MBAR_WAIT(empty[buf], phe[buf]); phe[buf] ^= 1;
                MBAR_EXPECT(full[buf], 32768);
                TMA_LD2D(sA, &tmA, (kc + 2) * 32, m0, full[buf]);
                TMA_LD2D(sB, &tmB, (kc + 2) * 32, n0, full[buf]);
            }
        }
        asm volatile(
            "tcgen05.commit.cta_group::1.mbarrier::arrive::one.shared::cluster.b64 [%0];"
            :: "r"(smem_u32(&s_mbar[4])) : "memory");
    }
    MBAR_WAIT(smem_u32(&s_mbar[4]), 0);
    asm volatile("tcgen05.fence::after_thread_sync;" ::: "memory");
    __syncthreads();

    // ---- coalesced epilogue (stage smem reused as transpose patch) ----
    if (wid < 4) {
        float* spatch = (float*)tptr + wid * (32 * 33);
        int mrow = m0 + wid * 32;
        float alphav = (epi == 1) ? alpha[0] : 0.f;
        for (int c0 = 0; c0 < 128; c0 += 32) {
            uint32_t r[32];
            LDTM_X32(r, tmem + c0);
            asm volatile("tcgen05.wait::ld.sync.aligned;" ::: "memory");
            #pragma unroll
            for (int j = 0; j < 32; j++) spatch[lid * 33 + j] = __uint_as_float(r[j]);
            __syncwarp();
            #pragma unroll
            for (int i = 0; i < 8; i++) {
                int rr = i * 4 + (lid >> 3);
                int c4 = (lid & 7) * 4;
                int m = mrow + rr;
                int n = n0 + c0 + c4;
                float vv[4];
                #pragma unroll
                for (int e = 0; e < 4; e++) vv[e] = spatch[rr * 33 + c4 + e];
                float4 bb = *(const float4*)(bias + n);
                vv[0] += bb.x; vv[1] += bb.y; vv[2] += bb.z; vv[3] += bb.w;
                if (epi == 1) {
                    float4 r4 = *(const float4*)(res + (size_t)m * N + n);
                    float4 g4 = *(const float4*)(gam + n);
                    float4 b4 = *(const float4*)(bet + n);
                    float4 u4 = *(const float4*)(rm + n);
                    float4 s4 = *(const float4*)(rv + n);
                    float y;
                    y = r4.x + vv[0]; vv[0] = (y - u4.x) * (g4.x * rsqrtf(s4.x + EPSL)) + b4.x + alphav * y;
                    y = r4.y + vv[1]; vv[1] = (y - u4.y) * (g4.y * rsqrtf(s4.y + EPSL)) + b4.y + alphav * y;
                    y = r4.z + vv[2]; vv[2] = (y - u4.z) * (g4.z * rsqrtf(s4.z + EPSL)) + b4.z + alphav * y;
                    y = r4.w + vv[3]; vv[3] = (y - u4.w) * (g4.w * rsqrtf(s4.w + EPSL)) + b4.w + alphav * y;
                } else if (epi == 2) {
                    int bidx = m / NN;
                    float sw_ = saw[bidx], sbv = sab[bidx];
                    #pragma unroll
                    for (int e = 0; e < 4; e++) {
                        float w = sw_ * vv[e] + sbv;
                        vv[e] = vv[e] / (1.f + __expf(-w * vv[e]));
                    }
                }
                *(float4*)(out + (size_t)m * N + n) = make_float4(vv[0], vv[1], vv[2], vv[3]);
            }
            __syncwarp();
        }
    }
    __syncthreads();
    if (tid == 0)
        for (int i = 0; i < 5; i++)
            asm volatile("mbarrier.inval.shared.b64 [%0];" :: "r"(smem_u32(&s_mbar[i])) : "memory");
    __syncthreads();
    if (wid == 0)
        asm volatile("tcgen05.dealloc.cta_group::1.sync.aligned.b32 %0, %1;"
                     :: "r"(tmem), "r"(128));
#endif
}

// ---------------- TMA wide GEMM 128x256 (FFN2): single hbuf read, BCN out -----
__global__ __launch_bounds__(256)
void k_tgemm_w(const __grid_constant__ CUtensorMap tmA,
               const __grid_constant__ CUtensorMap tmB,
               const float* __restrict__ bias, float* __restrict__ out,
               int K,
               const float* __restrict__ res,
               const float* __restrict__ gam, const float* __restrict__ bet,
               const float* __restrict__ rm,  const float* __restrict__ rv,
               const float* __restrict__ alpha)
{
#if TC_OK
    extern __shared__ char smem_raw[];
    __shared__ uint64_t s_mbar[5];
    __shared__ uint32_t s_tmem;

    uint32_t sb_raw = smem_u32(smem_raw);
    uint32_t tbase = (sb_raw + 1023u) & ~1023u;
    char* tptr = smem_raw + (tbase - sb_raw);

    int tid = threadIdx.x;
    int wid = tid >> 5, lid = tid & 31;
    int m0 = blockIdx.x * 128;
    const int N = 256;

    if (wid == 0)
        asm volatile("tcgen05.alloc.cta_group::1.sync.aligned.shared::cta.b32 [%0], %1;"
                     :: "r"(smem_u32(&s_tmem)), "r"(256) : "memory");
    if (tid == 0)
        for (int i = 0; i < 5; i++) MBAR_INIT(smem_u32(&s_mbar[i]), 1);
    __syncthreads();
    uint32_t tmem = s_tmem;
    if (wid == 0)
        asm volatile("tcgen05.relinquish_alloc_permit.cta_group::1.sync.aligned;");

    const uint32_t IDESC = (1u << 4) | (2u << 7) | (2u << 10) | (32u << 17) | (8u << 24);
    const int KC = K >> 5;

    if (tid == 0) {
        uint32_t full[2]  = { smem_u32(&s_mbar[0]), smem_u32(&s_mbar[1]) };
        uint32_t empty[2] = { smem_u32(&s_mbar[2]), smem_u32(&s_mbar[3]) };
        int phf[2] = {0, 0}, phe[2] = {0, 0};
        #pragma unroll
        for (int p = 0; p < 2; p++) {
            uint32_t sA = tbase + p * 49152, sB = sA + 16384;
            MBAR_EXPECT(full[p], 49152);
            TMA_LD2D(sA, &tmA, p * 32, m0, full[p]);
            TMA_LD2D(sB, &tmB, p * 32, 0, full[p]);
        }
        for (int kc = 0; kc < KC; kc++) {
            int buf = kc & 1;
            uint32_t sA = tbase + buf * 49152, sB = sA + 16384;
            MBAR_WAIT(full[buf], phf[buf]); phf[buf] ^= 1;
            uint64_t ad = DESC_BASE | ((uint64_t)(sA >> 4) & 0x3FFF);
            uint64_t bd = DESC_BASE | ((uint64_t)(sB >> 4) & 0x3FFF);
            #pragma unroll
            for (int s = 0; s < 4; s++)
                mma_tf32(tmem, ad + s * 2, bd + s * 2, IDESC, (kc > 0) || (s > 0));
            asm volatile(
                "tcgen05.commit.cta_group::1.mbarrier::arrive::one.shared::cluster.b64 [%0];"
                :: "r"(empty[buf]) : "memory");
            if (kc + 2 < KC) {
                MBAR_WAIT(empty[buf], phe[buf]); phe[buf] ^= 1;
                MBAR_EXPECT(full[buf], 49152);
                TMA_LD2D(sA, &tmA, (kc + 2) * 32, m0, full[buf]);
                TMA_LD2D(sB, &tmB, (kc + 2) * 32, 0, full[buf]);
            }
        }
        asm volatile(
            "tcgen05.commit.cta_group::1.mbarrier::arrive::one.shared::cluster.b64 [%0];"
            :: "r"(smem_u32(&s_mbar[4])) : "memory");
    }
    MBAR_WAIT(smem_u32(&s_mbar[4]), 0);
    asm volatile("tcgen05.fence::after_thread_sync;" ::: "memory");
    __syncthreads();

    // epilogue: +bias, repbn(res+v), write [B,C,N]
    if (wid < 4) {
        float* spatch = (float*)tptr + wid * (32 * 33);
        int mrow = m0 + wid * 32;
        float alphav = alpha[0];
        int m_out = mrow + lid;
        int b_o = m_out / NN, nsp = m_out % NN;
        size_t obase = (size_t)b_o * CC * NN + nsp;
        for (int c0 = 0; c0 < 256; c0 += 32) {
            uint32_t r[32];
            LDTM_X32(r, tmem + c0);
            asm volatile("tcgen05.wait::ld.sync.aligned;" ::: "memory");
            #pragma unroll
            for (int j = 0; j < 32; j++) spatch[lid * 33 + j] = __uint_as_float(r[j]);
            __syncwarp();
            #pragma unroll
            for (int i = 0; i < 8; i++) {
                int rr = i * 4 + (lid >> 3);
                int c4 = (lid & 7) * 4;
                int m = mrow + rr;
                int n = c0 + c4;
                float vv[4];
                #pragma unroll
                for (int e = 0; e < 4; e++) vv[e] = spatch[rr * 33 + c4 + e];
                float4 bb = *(const float4*)(bias + n);
                float4 r4 = *(const float4*)(res + (size_t)m * N + n);
                float4 g4 = *(const float4*)(gam + n);
                float4 b4 = *(const float4*)(bet + n);
                float4 u4 = *(const float4*)(rm + n);
                float4 s4 = *(const float4*)(rv + n);
                float y;
                y = r4.x + vv[0] + bb.x; vv[0] = (y - u4.x) * (g4.x * rsqrtf(s4.x + EPSL)) + b4.x + alphav * y;
                y = r4.y + vv[1] + bb.y; vv[1] = (y - u4.y) * (g4.y * rsqrtf(s4.y + EPSL)) + b4.y + alphav * y;
                y = r4.z + vv[2] + bb.z; vv[2] = (y - u4.z) * (g4.z * rsqrtf(s4.z + EPSL)) + b4.z + alphav * y;
                y = r4.w + vv[3] + bb.w; vv[3] = (y - u4.w) * (g4.w * rsqrtf(s4.w + EPSL)) + b4.w + alphav * y;
                #pragma unroll
                for (int e = 0; e < 4; e++) spatch[rr * 33 + c4 + e] = vv[e];
            }
            __syncwarp();
            #pragma unroll
            for (int cc = 0; cc < 32; cc++)
                out[obase + (size_t)(c0 + cc) * NN] = spatch[lid * 33 + cc];
            __syncwarp();
        }
    }
    __syncthreads();
    if (tid == 0)
        for (int i = 0; i < 5; i++)
            asm volatile("mbarrier.inval.shared.b64 [%0];" :: "r"(smem_u32(&s_mbar[i])) : "memory");
    __syncthreads();
    if (wid == 0)
        asm volatile("tcgen05.dealloc.cta_group::1.sync.aligned.b32 %0, %1;"
                     :: "r"(tmem), "r"(256));
#endif
}

// ---------------- attention: one block per (head, batch) ----------------------
__global__ void k_attn(const float* __restrict__ qkv, float* __restrict__ attnout) {
    extern __shared__ float sh[];
    float4* Ks = (float4*)sh;
    float4* Vs = (float4*)(sh + NN * 32);
    int h = blockIdx.x, b = blockIdx.y;
    int tid = threadIdx.x;
    size_t base = (size_t)b * NN * 768;
    int koff = 256 + h * 32, voff = 512 + h * 32;
    for (int i = tid; i < NN * 8; i += 256) {
        int m = i >> 3, d = i & 7;
        Ks[i] = *(const float4*)(qkv + base + (size_t)m * 768 + koff + d * 4);
        Vs[i] = *(const float4*)(qkv + base + (size_t)m * 768 + voff + d * 4);
    }
    __syncthreads();
    if (tid < NN) {
        float4 q4[8], o4[8];
        const float* qp = qkv + base + (size_t)tid * 768 + h * 32;
        #pragma unroll
        for (int i = 0; i < 8; i++) {
            float4 qv = *(const float4*)(qp + i * 4);
            const float sc = 0.17677669529663687f;
            q4[i] = make_float4(qv.x * sc, qv.y * sc, qv.z * sc, qv.w * sc);
            o4[i] = make_float4(0.f, 0.f, 0.f, 0.f);
        }
        float mx = -1e30f, l = 0.f;
        for (int m = 0; m < NN; m += 2) {
            const float4* k0 = Ks + m * 8;
            const float4* k1 = k0 + 8;
            float s0 = 0.f, s1 = 0.f;
            #pragma unroll
            for (int i = 0; i < 8; i++) {
                float4 a = q4[i], x0 = k0[i], x1 = k1[i];
                s0 += a.x * x0.x + a.y * x0.y + a.z * x0.z + a.w * x0.w;
                s1 += a.x * x1.x + a.y * x1.y + a.z * x1.z + a.w * x1.w;
            }
            float nm = fmaxf(mx, fmaxf(s0, s1));
            float f  = __expf(mx - nm);
            float p0 = __expf(s0 - nm);
            float p1 = __expf(s1 - nm);
            l = l * f + p0 + p1;
            const float4* v0 = Vs + m * 8;
            const float4* v1 = v0 + 8;
            #pragma unroll
            for (int i = 0; i < 8; i++) {
                float4 o = o4[i], a = v0[i], c = v1[i];
                o.x = o.x * f + p0 * a.x + p1 * c.x;
                o.y = o.y * f + p0 * a.y + p1 * c.y;
                o.z = o.z * f + p0 * a.z + p1 * c.z;
                o.w = o.w * f + p0 * a.w + p1 * c.w;
                o4[i] = o;
            }
            mx = nm;
        }
        float inv = 1.f / l;
        float* op = attnout + ((size_t)(b * NN + tid)) * CC + h * 32;
        #pragma unroll
        for (int i = 0; i < 8; i++) {
            float4 o = o4[i];
            *(float4*)(op + i * 4) = make_float4(o.x * inv, o.y * inv, o.z * inv, o.w * inv);
        }
    }
}

// ---------------- host: tensormap encode --------------------------------------
typedef CUresult (*PFN_encodeTiled)(
    CUtensorMap*, CUtensorMapDataType, cuuint32_t, void*,
    const cuuint64_t*, const cuuint64_t*, const cuuint32_t*, const cuuint32_t*,
    CUtensorMapInterleave, CUtensorMapSwizzle, CUtensorMapL2promotion,
    CUtensorMapFloatOOBfill);

static void encode_2d(PFN_encodeTiled enc, CUtensorMap* tm, void* base,
                      uint64_t rows, uint64_t cols, uint32_t box_rows) {
    cuuint64_t dims[2]    = { cols, rows };
    cuuint64_t strides[1] = { cols * 4 };
    cuuint32_t box[2]     = { 32, box_rows };   // 32 f32 = 128B (SW128 limit)
    cuuint32_t estr[2]    = { 1, 1 };
    enc(tm, CU_TENSOR_MAP_DATA_TYPE_FLOAT32, 2, base, dims, strides, box, estr,
        CU_TENSOR_MAP_INTERLEAVE_NONE, CU_TENSOR_MAP_SWIZZLE_128B,
        CU_TENSOR_MAP_L2_PROMOTION_L2_128B, CU_TENSOR_MAP_FLOAT_OOB_FILL_NONE);
}

// ---------------- launch ------------------------------------------------------
extern "C" void kernel_launch(void* const* d_in, const int* in_sizes, int n_in,
                              void* d_out, int out_size) {
    const float* x      = (const float*)d_in[0];
    const float* W_qkv  = (const float*)d_in[1];
    const float* b_qkv  = (const float*)d_in[2];
    const float* W_proj = (const float*)d_in[3];
    const float* b_proj = (const float*)d_in[4];
    const float* W1     = (const float*)d_in[5];
    const float* b1     = (const float*)d_in[6];
    const float* W2     = (const float*)d_in[7];
    const float* b2     = (const float*)d_in[8];
    const float* sa_w   = (const float*)d_in[9];
    const float* sa_b   = (const float*)d_in[10];
    const float* alpha1 = (const float*)d_in[11];
    const float* gamma1 = (const float*)d_in[12];
    const float* beta1  = (const float*)d_in[13];
    const float* rm1    = (const float*)d_in[14];
    const float* rv1    = (const float*)d_in[15];
    const float* alpha2 = (const float*)d_in[16];
    const float* gamma2 = (const float*)d_in[17];
    const float* beta2  = (const float*)d_in[18];
    const float* rm2    = (const float*)d_in[19];
    const float* rv2    = (const float*)d_in[20];
    float* out = (float*)d_out;

    float *t, *qkv, *attn, *t1, *hbuf, *wqkvT, *wprojT, *w1T, *w2T;
    cudaGetSymbolAddress((void**)&t,      g_t);
    cudaGetSymbolAddress((void**)&qkv,    g_qkv);
    cudaGetSymbolAddress((void**)&attn,   g_attn);
    cudaGetSymbolAddress((void**)&t1,     g_t1);
    cudaGetSymbolAddress((void**)&hbuf,   g_h);
    cudaGetSymbolAddress((void**)&wqkvT,  g_wqkvT);
    cudaGetSymbolAddress((void**)&wprojT, g_wprojT);
    cudaGetSymbolAddress((void**)&w1T,    g_w1T);
    cudaGetSymbolAddress((void**)&w2T,    g_w2T);

    // driver entry point for tensormap encoding (no -lcuda needed)
    void* fn = nullptr;
    cudaDriverEntryPointQueryResult qres;
    cudaGetDriverEntryPoint("cuTensorMapEncodeTiled", &fn, cudaEnableDefault, &qres);
    PFN_encodeTiled enc = (PFN_encodeTiled)fn;

    CUtensorMap tm_t, tm_wqkv, tm_attn, tm_wproj, tm_t1, tm_w1, tm_h, tm_w2;
    encode_2d(enc, &tm_t,     t,      MM,   256,  128);
    encode_2d(enc, &tm_wqkv,  wqkvT,  768,  256,  128);
    encode_2d(enc, &tm_attn,  attn,   MM,   256,  128);
    encode_2d(enc, &tm_wproj, wprojT, 256,  256,  128);
    encode_2d(enc, &tm_t1,    t1,     MM,   256,  128);
    encode_2d(enc, &tm_w1,    w1T,    CMID, 256,  128);
    encode_2d(enc, &tm_h,     hbuf,   MM,   CMID, 128);
    encode_2d(enc, &tm_w2,    w2T,    256,  CMID, 256);

    const int GEMM_SMEM  = 1024 + 2 * 32768;   // 66560
    const int GEMMW_SMEM = 1024 + 2 * 49152;   // 99328
    cudaFuncSetAttribute(k_tgemm,   cudaFuncAttributeMaxDynamicSharedMemorySize, GEMM_SMEM);
    cudaFuncSetAttribute(k_tgemm_w, cudaFuncAttributeMaxDynamicSharedMemorySize, GEMMW_SMEM);
    cudaFuncSetAttribute(k_attn,    cudaFuncAttributeMaxDynamicSharedMemorySize, 2 * NN * 32 * 4);

    dim3 tb(32, 8);
    k_wt<<<dim3(768 / 32, 256 / 32), tb>>>(W_qkv, wqkvT, 256, 768);
    k_wt<<<dim3(256 / 32, 256 / 32), tb>>>(W_proj, wprojT, 256, 256);
    k_wt<<<dim3(CMID / 32, 256 / 32), tb>>>(W1, w1T, 256, CMID);
    k_wt<<<dim3(256 / 32, CMID / 32), tb>>>(W2, w2T, CMID, 256);
    k_in_transpose<<<dim3(7, 8, BB), tb>>>(x, t);
    // QKV
    k_tgemm<<<dim3(768 / 128, MM / 128), 256, GEMM_SMEM>>>(tm_t, tm_wqkv, b_qkv, qkv,
        768, 256, 0, nullptr, nullptr, nullptr, nullptr, nullptr, nullptr, nullptr, nullptr);
    k_attn<<<dim3(8, BB), 256, 2 * NN * 32 * 4>>>(qkv, attn);
    // proj + residual + repbn1
    k_tgemm<<<dim3(256 / 128, MM / 128), 256, GEMM_SMEM>>>(tm_attn, tm_wproj, b_proj, t1,
        256, 256, 1, t, gamma1, beta1, rm1, rv1, alpha1, nullptr, nullptr);
    // FFN1 + SpatialSILU
    k_tgemm<<<dim3(CMID / 128, MM / 128), 256, GEMM_SMEM>>>(tm_t1, tm_w1, b1, hbuf,
        CMID, 256, 2, nullptr, nullptr, nullptr, nullptr, nullptr, nullptr, sa_w, sa_b);
    // FFN2 (wide) + residual + repbn2 -> [B,C,N]
    k_tgemm_w<<<MM / 128, 256, GEMMW_SMEM>>>(tm_h, tm_w2, b2, out,
        CMID, t1, gamma2, beta2, rm2, rv2, alpha2);
}

// round 10
// speedup vs baseline: 1.9573x; 1.2002x over previous
#include <cuda_runtime.h>
#include <cuda.h>
#include <cstdint>
#include <math.h>

#define BB 256
#define CC 256
#define NN 196
#define MM (BB*NN)        // 50176
#define CMID 2048
#define EPSL 1e-5f

#if defined(__CUDA_ARCH_FEAT_SM103_ALL) || defined(__CUDA_ARCH_FEAT_SM100_ALL) || defined(__CUDA_ARCH_FEAT_SM101_ALL)
#define TC_OK 1
#else
#define TC_OK 0
#endif

// ---------------- scratch (device globals) -----------------------------------
__device__ float g_t   [(size_t)MM*CC];
__device__ float g_qkv [(size_t)MM*3*CC];
__device__ float g_attn[(size_t)MM*CC];
__device__ float g_t1  [(size_t)MM*CC];
__device__ float g_h   [(size_t)MM*CMID];
__device__ float g_wqkvT[(size_t)3*CC*CC];   // [768,256]
__device__ float g_wprojT[(size_t)CC*CC];    // [256,256]
__device__ float g_w1T  [(size_t)CMID*CC];   // [2048,256]
__device__ float g_w2T  [(size_t)CC*CMID];   // [256,2048]

// ---------------- PTX helpers -------------------------------------------------
__device__ __forceinline__ uint32_t smem_u32(const void* p) {
    uint32_t a;
    asm("{ .reg .u64 t; cvta.to.shared.u64 t, %1; cvt.u32.u64 %0, t; }" : "=r"(a) : "l"(p));
    return a;
}

#define MBAR_INIT(addr, cnt) \
    asm volatile("mbarrier.init.shared.b64 [%0], %1;" :: "r"(addr), "r"(cnt) : "memory")

#define MBAR_WAIT(addr, parity) do {                                              \
    uint32_t _m = (addr); uint32_t _p = (parity); uint32_t _d;                    \
    asm volatile("{\n\t.reg .pred p;\n\t"                                         \
        "mbarrier.try_wait.parity.acquire.cta.shared::cta.b64 p, [%1], %2;\n\t"   \
        "selp.b32 %0, 1, 0, p;\n\t}" : "=r"(_d) : "r"(_m), "r"(_p) : "memory");   \
    if (!_d) {                                                                     \
        asm volatile("{\n\t.reg .pred P1;\n\t"                                     \
            "W_%=:\n\t"                                                            \
            "mbarrier.try_wait.parity.acquire.cta.shared::cta.b64 P1, [%0], %1, 0x989680;\n\t" \
            "@P1 bra.uni D_%=;\n\t"                                                \
            "bra.uni W_%=;\n\t"                                                    \
            "D_%=:\n\t}" :: "r"(_m), "r"(_p) : "memory");                          \
    } } while (0)

#if TC_OK
#define MBAR_EXPECT(mbar, bytes) \
    asm volatile("mbarrier.arrive.expect_tx.shared.b64 _, [%0], %1;" \
                 :: "r"(mbar), "r"(bytes) : "memory")

#define TMA_LD2D(smem, tmapp, c0, c1, mbar) \
    asm volatile("cp.async.bulk.tensor.2d.shared::cta.global.tile.mbarrier::complete_tx::bytes " \
                 "[%0], [%1, {%2, %3}], [%4];" \
                 :: "r"(smem), "l"(tmapp), "r"(c0), "r"(c1), "r"(mbar) : "memory")

__device__ __forceinline__ void mma_tf32(uint32_t d, uint64_t ad, uint64_t bd,
                                         uint32_t idesc, bool acc) {
    uint32_t e = acc ? 1u : 0u;
    asm volatile(
        "{\n\t.reg .pred p;\n\tsetp.ne.u32 p, %5, 0;\n\t"
        "tcgen05.mma.cta_group::1.kind::tf32 [%0], %1, %2, %3, {%4, %4, %4, %4}, p;\n\t}"
        :: "r"(d), "l"(ad), "l"(bd), "r"(idesc), "r"(0u), "r"(e) : "memory");
}

#define LDTM_X32(r, addr)                                                         \
    asm volatile("tcgen05.ld.sync.aligned.32x32b.x32.b32 "                        \
        "{%0, %1, %2, %3, %4, %5, %6, %7, %8, %9, %10, %11, %12, %13, %14, %15, " \
        " %16, %17, %18, %19, %20, %21, %22, %23, %24, %25, %26, %27, %28, %29, %30, %31}, [%32];" \
        : "=r"((r)[0]), "=r"((r)[1]), "=r"((r)[2]), "=r"((r)[3]),                 \
          "=r"((r)[4]), "=r"((r)[5]), "=r"((r)[6]), "=r"((r)[7]),                 \
          "=r"((r)[8]), "=r"((r)[9]), "=r"((r)[10]), "=r"((r)[11]),               \
          "=r"((r)[12]), "=r"((r)[13]), "=r"((r)[14]), "=r"((r)[15]),             \
          "=r"((r)[16]), "=r"((r)[17]), "=r"((r)[18]), "=r"((r)[19]),             \
          "=r"((r)[20]), "=r"((r)[21]), "=r"((r)[22]), "=r"((r)[23]),             \
          "=r"((r)[24]), "=r"((r)[25]), "=r"((r)[26]), "=r"((r)[27]),             \
          "=r"((r)[28]), "=r"((r)[29]), "=r"((r)[30]), "=r"((r)[31])              \
        : "r"(addr))
#endif

static constexpr uint64_t DESC_BASE =
    (uint64_t(2) << 61) | (uint64_t(1) << 46) | (uint64_t(64) << 32) | (uint64_t(1) << 16);

// ---------------- transpose x [B][C][N] -> t [B*N][C] -------------------------
__global__ void k_in_transpose(const float* __restrict__ x, float* __restrict__ t) {
    __shared__ float tile[32][33];
    int b = blockIdx.z;
    int n0 = blockIdx.x * 32, c0 = blockIdx.y * 32;
    int tx = threadIdx.x, ty = threadIdx.y;
    const float* xb = x + (size_t)b * CC * NN;
    #pragma unroll
    for (int j = 0; j < 32; j += 8) {
        int c = c0 + ty + j, n = n0 + tx;
        if (n < NN) tile[ty + j][tx] = xb[(size_t)c * NN + n];
    }
    __syncthreads();
    #pragma unroll
    for (int j = 0; j < 32; j += 8) {
        int n = n0 + ty + j, c = c0 + tx;
        if (n < NN) t[((size_t)b * NN + n) * CC + c] = tile[tx][ty + j];
    }
}

// ---------------- weight transpose W[R,C] -> Wt[C,R] --------------------------
__global__ void k_wt(const float* __restrict__ W, float* __restrict__ Wt, int R, int C) {
    __shared__ float tile[32][33];
    int c0 = blockIdx.x * 32, r0 = blockIdx.y * 32;
    int tx = threadIdx.x, ty = threadIdx.y;
    #pragma unroll
    for (int j = 0; j < 32; j += 8)
        tile[ty + j][tx] = W[(size_t)(r0 + ty + j) * C + c0 + tx];
    __syncthreads();
    #pragma unroll
    for (int j = 0; j < 32; j += 8)
        Wt[(size_t)(c0 + ty + j) * R + r0 + tx] = tile[tx][ty + j];
}

// ---------------- TMA tcgen05 tf32 GEMM 128x128: out = A @ Bt^T + epilogue ----
// epi 0: +bias ; epi 1: +bias, repbn(res+v) ; epi 2: +bias, SpatialSILU
__global__ __launch_bounds__(256)
void k_tgemm(const __grid_constant__ CUtensorMap tmA,
             const __grid_constant__ CUtensorMap tmB,
             const float* __restrict__ bias, float* __restrict__ out,
             int N, int K, int epi,
             const float* __restrict__ res,
             const float* __restrict__ gam, const float* __restrict__ bet,
             const float* __restrict__ rm,  const float* __restrict__ rv,
             const float* __restrict__ alpha,
             const float* __restrict__ saw, const float* __restrict__ sab)
{
#if TC_OK
    extern __shared__ char smem_raw[];
    __shared__ uint64_t s_mbar[5];   // full0, full1, empty0, empty1, done
    __shared__ uint32_t s_tmem;

    uint32_t sb_raw = smem_u32(smem_raw);
    uint32_t tbase = (sb_raw + 1023u) & ~1023u;
    char* tptr = smem_raw + (tbase - sb_raw);

    int tid = threadIdx.x;
    int wid = tid >> 5, lid = tid & 31;
    int m0 = blockIdx.y * 128, n0 = blockIdx.x * 128;

    if (wid == 0)
        asm volatile("tcgen05.alloc.cta_group::1.sync.aligned.shared::cta.b32 [%0], %1;"
                     :: "r"(smem_u32(&s_tmem)), "r"(128) : "memory");
    if (tid == 0)
        for (int i = 0; i < 5; i++) MBAR_INIT(smem_u32(&s_mbar[i]), 1);
    __syncthreads();
    uint32_t tmem = s_tmem;
    if (wid == 0)
        asm volatile("tcgen05.relinquish_alloc_permit.cta_group::1.sync.aligned;");

    const uint32_t IDESC = (1u << 4) | (2u << 7) | (2u << 10) | (16u << 17) | (8u << 24);
    const int KC = K >> 5;

    if (tid == 0) {
        uint32_t full[2]  = { smem_u32(&s_mbar[0]), smem_u32(&s_mbar[1]) };
        uint32_t empty[2] = { smem_u32(&s_mbar[2]), smem_u32(&s_mbar[3]) };
        int phf[2] = {0, 0}, phe[2] = {0, 0};
        #pragma unroll
        for (int p = 0; p < 2; p++) {
            uint32_t sA = tbase + p * 32768, sB = sA + 16384;
            MBAR_EXPECT(full[p], 32768);
            TMA_LD2D(sA, &tmA, p * 32, m0, full[p]);
            TMA_LD2D(sB, &tmB, p * 32, n0, full[p]);
        }
        for (int kc = 0; kc < KC; kc++) {
            int buf = kc & 1;
            uint32_t sA = tbase + buf * 32768, sB = sA + 16384;
            MBAR_WAIT(full[buf], phf[buf]); phf[buf] ^= 1;
            uint64_t ad = DESC_BASE | ((uint64_t)(sA >> 4) & 0x3FFF);
            uint64_t bd = DESC_BASE | ((uint64_t)(sB >> 4) & 0x3FFF);
            #pragma unroll
            for (int s = 0; s < 4; s++)
                mma_tf32(tmem, ad + s * 2, bd + s * 2, IDESC, (kc > 0) || (s > 0));
            asm volatile(
                "tcgen05.commit.cta_group::1.mbarrier::arrive::one.shared::cluster.b64 [%0];"
                :: "r"(empty[buf]) : "memory");
            if (kc + 2 < KC) {
                MBAR_WAIT(empty[buf], phe[buf]); phe[buf] ^= 1;
                MBAR_EXPECT(full[buf], 32768);
                TMA_LD2D(sA, &tmA, (kc + 2) * 32, m0, full[buf]);
                TMA_LD2D(sB, &tmB, (kc + 2) * 32, n0, full[buf]);
            }
        }
        asm volatile(
            "tcgen05.commit.cta_group::1.mbarrier::arrive::one.shared::cluster.b64 [%0];"
            :: "r"(smem_u32(&s_mbar[4])) : "memory");
    }
    MBAR_WAIT(smem_u32(&s_mbar[4]), 0);
    asm volatile("tcgen05.fence::after_thread_sync;" ::: "memory");
    __syncthreads();

    // ---- 8-warp coalesced epilogue: warp w -> rows (w&3)*32, cols (w>>2)*64 --
    {
        int sub = wid & 3, half = wid >> 2;
        float* spatch = (float*)tptr + wid * (32 * 33);
        int mrow = m0 + sub * 32;
        float alphav = (epi == 1) ? alpha[0] : 0.f;
        #pragma unroll
        for (int cb = 0; cb < 2; cb++) {
            int c0 = half * 64 + cb * 32;
            uint32_t r[32];
            LDTM_X32(r, tmem + c0);
            asm volatile("tcgen05.wait::ld.sync.aligned;" ::: "memory");
            #pragma unroll
            for (int j = 0; j < 32; j++) spatch[lid * 33 + j] = __uint_as_float(r[j]);
            __syncwarp();
            #pragma unroll
            for (int i = 0; i < 8; i++) {
                int rr = i * 4 + (lid >> 3);
                int c4 = (lid & 7) * 4;
                int m = mrow + rr;
                int n = n0 + c0 + c4;
                float vv[4];
                #pragma unroll
                for (int e = 0; e < 4; e++) vv[e] = spatch[rr * 33 + c4 + e];
                float4 bb = *(const float4*)(bias + n);
                vv[0] += bb.x; vv[1] += bb.y; vv[2] += bb.z; vv[3] += bb.w;
                if (epi == 1) {
                    float4 r4 = *(const float4*)(res + (size_t)m * N + n);
                    float4 g4 = *(const float4*)(gam + n);
                    float4 b4 = *(const float4*)(bet + n);
                    float4 u4 = *(const float4*)(rm + n);
                    float4 s4 = *(const float4*)(rv + n);
                    float y;
                    y = r4.x + vv[0]; vv[0] = (y - u4.x) * (g4.x * rsqrtf(s4.x + EPSL)) + b4.x + alphav * y;
                    y = r4.y + vv[1]; vv[1] = (y - u4.y) * (g4.y * rsqrtf(s4.y + EPSL)) + b4.y + alphav * y;
                    y = r4.z + vv[2]; vv[2] = (y - u4.z) * (g4.z * rsqrtf(s4.z + EPSL)) + b4.z + alphav * y;
                    y = r4.w + vv[3]; vv[3] = (y - u4.w) * (g4.w * rsqrtf(s4.w + EPSL)) + b4.w + alphav * y;
                } else if (epi == 2) {
                    int bidx = m / NN;
                    float sw_ = saw[bidx], sbv = sab[bidx];
                    #pragma unroll
                    for (int e = 0; e < 4; e++) {
                        float w = sw_ * vv[e] + sbv;
                        vv[e] = vv[e] / (1.f + __expf(-w * vv[e]));
                    }
                }
                *(float4*)(out + (size_t)m * N + n) = make_float4(vv[0], vv[1], vv[2], vv[3]);
            }
            __syncwarp();
        }
    }
    __syncthreads();
    if (tid == 0)
        for (int i = 0; i < 5; i++)
            asm volatile("mbarrier.inval.shared.b64 [%0];" :: "r"(smem_u32(&s_mbar[i])) : "memory");
    __syncthreads();
    if (wid == 0)
        asm volatile("tcgen05.dealloc.cta_group::1.sync.aligned.b32 %0, %1;"
                     :: "r"(tmem), "r"(128));
#endif
}

// ---------------- TMA wide GEMM 128x256 (FFN2): single hbuf read, BCN out -----
__global__ __launch_bounds__(256)
void k_tgemm_w(const __grid_constant__ CUtensorMap tmA,
               const __grid_constant__ CUtensorMap tmB,
               const float* __restrict__ bias, float* __restrict__ out,
               int K,
               const float* __restrict__ res,
               const float* __restrict__ gam, const float* __restrict__ bet,
               const float* __restrict__ rm,  const float* __restrict__ rv,
               const float* __restrict__ alpha)
{
#if TC_OK
    extern __shared__ char smem_raw[];
    __shared__ uint64_t s_mbar[5];
    __shared__ uint32_t s_tmem;

    uint32_t sb_raw = smem_u32(smem_raw);
    uint32_t tbase = (sb_raw + 1023u) & ~1023u;
    char* tptr = smem_raw + (tbase - sb_raw);

    int tid = threadIdx.x;
    int wid = tid >> 5, lid = tid & 31;
    int m0 = blockIdx.x * 128;
    const int N = 256;

    if (wid == 0)
        asm volatile("tcgen05.alloc.cta_group::1.sync.aligned.shared::cta.b32 [%0], %1;"
                     :: "r"(smem_u32(&s_tmem)), "r"(256) : "memory");
    if (tid == 0)
        for (int i = 0; i < 5; i++) MBAR_INIT(smem_u32(&s_mbar[i]), 1);
    __syncthreads();
    uint32_t tmem = s_tmem;
    if (wid == 0)
        asm volatile("tcgen05.relinquish_alloc_permit.cta_group::1.sync.aligned;");

    const uint32_t IDESC = (1u << 4) | (2u << 7) | (2u << 10) | (32u << 17) | (8u << 24);
    const int KC = K >> 5;

    if (tid == 0) {
        uint32_t full[2]  = { smem_u32(&s_mbar[0]), smem_u32(&s_mbar[1]) };
        uint32_t empty[2] = { smem_u32(&s_mbar[2]), smem_u32(&s_mbar[3]) };
        int phf[2] = {0, 0}, phe[2] = {0, 0};
        #pragma unroll
        for (int p = 0; p < 2; p++) {
            uint32_t sA = tbase + p * 49152, sB = sA + 16384;
            MBAR_EXPECT(full[p], 49152);
            TMA_LD2D(sA, &tmA, p * 32, m0, full[p]);
            TMA_LD2D(sB, &tmB, p * 32, 0, full[p]);
        }
        for (int kc = 0; kc < KC; kc++) {
            int buf = kc & 1;
            uint32_t sA = tbase + buf * 49152, sB = sA + 16384;
            MBAR_WAIT(full[buf], phf[buf]); phf[buf] ^= 1;
            uint64_t ad = DESC_BASE | ((uint64_t)(sA >> 4) & 0x3FFF);
            uint64_t bd = DESC_BASE | ((uint64_t)(sB >> 4) & 0x3FFF);
            #pragma unroll
            for (int s = 0; s < 4; s++)
                mma_tf32(tmem, ad + s * 2, bd + s * 2, IDESC, (kc > 0) || (s > 0));
            asm volatile(
                "tcgen05.commit.cta_group::1.mbarrier::arrive::one.shared::cluster.b64 [%0];"
                :: "r"(empty[buf]) : "memory");
            if (kc + 2 < KC) {
                MBAR_WAIT(empty[buf], phe[buf]); phe[buf] ^= 1;
                MBAR_EXPECT(full[buf], 49152);
                TMA_LD2D(sA, &tmA, (kc + 2) * 32, m0, full[buf]);
                TMA_LD2D(sB, &tmB, (kc + 2) * 32, 0, full[buf]);
            }
        }
        asm volatile(
            "tcgen05.commit.cta_group::1.mbarrier::arrive::one.shared::cluster.b64 [%0];"
            :: "r"(smem_u32(&s_mbar[4])) : "memory");
    }
    MBAR_WAIT(smem_u32(&s_mbar[4]), 0);
    asm volatile("tcgen05.fence::after_thread_sync;" ::: "memory");
    __syncthreads();

    // 8-warp epilogue: warp w -> rows (w&3)*32, cols (w>>2)*128 + cb*32
    {
        int sub = wid & 3, half = wid >> 2;
        float* spatch = (float*)tptr + wid * (32 * 33);
        int mrow = m0 + sub * 32;
        float alphav = alpha[0];
        int m_out = mrow + lid;
        int b_o = m_out / NN, nsp = m_out % NN;
        size_t obase = (size_t)b_o * CC * NN + nsp;
        #pragma unroll
        for (int cb = 0; cb < 4; cb++) {
            int c0 = half * 128 + cb * 32;
            uint32_t r[32];
            LDTM_X32(r, tmem + c0);
            asm volatile("tcgen05.wait::ld.sync.aligned;" ::: "memory");
            #pragma unroll
            for (int j = 0; j < 32; j++) spatch[lid * 33 + j] = __uint_as_float(r[j]);
            __syncwarp();
            #pragma unroll
            for (int i = 0; i < 8; i++) {
                int rr = i * 4 + (lid >> 3);
                int c4 = (lid & 7) * 4;
                int m = mrow + rr;
                int n = c0 + c4;
                float vv[4];
                #pragma unroll
                for (int e = 0; e < 4; e++) vv[e] = spatch[rr * 33 + c4 + e];
                float4 bb = *(const float4*)(bias + n);
                float4 r4 = *(const float4*)(res + (size_t)m * N + n);
                float4 g4 = *(const float4*)(gam + n);
                float4 b4 = *(const float4*)(bet + n);
                float4 u4 = *(const float4*)(rm + n);
                float4 s4 = *(const float4*)(rv + n);
                float y;
                y = r4.x + vv[0] + bb.x; vv[0] = (y - u4.x) * (g4.x * rsqrtf(s4.x + EPSL)) + b4.x + alphav * y;
                y = r4.y + vv[1] + bb.y; vv[1] = (y - u4.y) * (g4.y * rsqrtf(s4.y + EPSL)) + b4.y + alphav * y;
                y = r4.z + vv[2] + bb.z; vv[2] = (y - u4.z) * (g4.z * rsqrtf(s4.z + EPSL)) + b4.z + alphav * y;
                y = r4.w + vv[3] + bb.w; vv[3] = (y - u4.w) * (g4.w * rsqrtf(s4.w + EPSL)) + b4.w + alphav * y;
                #pragma unroll
                for (int e = 0; e < 4; e++) spatch[rr * 33 + c4 + e] = vv[e];
            }
            __syncwarp();
            #pragma unroll
            for (int cc = 0; cc < 32; cc++)
                out[obase + (size_t)(c0 + cc) * NN] = spatch[lid * 33 + cc];
            __syncwarp();
        }
    }
    __syncthreads();
    if (tid == 0)
        for (int i = 0; i < 5; i++)
            asm volatile("mbarrier.inval.shared.b64 [%0];" :: "r"(smem_u32(&s_mbar[i])) : "memory");
    __syncthreads();
    if (wid == 0)
        asm volatile("tcgen05.dealloc.cta_group::1.sync.aligned.b32 %0, %1;"
                     :: "r"(tmem), "r"(256));
#endif
}

// ---------------- attention: no-max softmax (|s| < ~0.6 guaranteed) -----------
__global__ void k_attn(const float* __restrict__ qkv, float* __restrict__ attnout) {
    extern __shared__ float sh[];
    float4* Ks = (float4*)sh;
    float4* Vs = (float4*)(sh + NN * 32);
    int h = blockIdx.x, b = blockIdx.y;
    int tid = threadIdx.x;
    size_t base = (size_t)b * NN * 768;
    int koff = 256 + h * 32, voff = 512 + h * 32;
    for (int i = tid; i < NN * 8; i += 256) {
        int m = i >> 3, d = i & 7;
        Ks[i] = *(const float4*)(qkv + base + (size_t)m * 768 + koff + d * 4);
        Vs[i] = *(const float4*)(qkv + base + (size_t)m * 768 + voff + d * 4);
    }
    __syncthreads();
    if (tid < NN) {
        float4 q4[8], o4[8];
        const float* qp = qkv + base + (size_t)tid * 768 + h * 32;
        #pragma unroll
        for (int i = 0; i < 8; i++) {
            float4 qv = *(const float4*)(qp + i * 4);
            const float sc = 0.17677669529663687f;
            q4[i] = make_float4(qv.x * sc, qv.y * sc, qv.z * sc, qv.w * sc);
            o4[i] = make_float4(0.f, 0.f, 0.f, 0.f);
        }
        float l = 0.f;
        for (int m = 0; m < NN; m += 2) {
            const float4* k0 = Ks + m * 8;
            const float4* k1 = k0 + 8;
            float s0 = 0.f, s1 = 0.f;
            #pragma unroll
            for (int i = 0; i < 8; i++) {
                float4 a = q4[i], x0 = k0[i], x1 = k1[i];
                s0 += a.x * x0.x + a.y * x0.y + a.z * x0.z + a.w * x0.w;
                s1 += a.x * x1.x + a.y * x1.y + a.z * x1.z + a.w * x1.w;
            }
            float p0 = __expf(s0);
            float p1 = __expf(s1);
            l += p0 + p1;
            const float4* v0 = Vs + m * 8;
            const float4* v1 = v0 + 8;
            #pragma unroll
            for (int i = 0; i < 8; i++) {
                float4 o = o4[i], a = v0[i], c = v1[i];
                o.x += p0 * a.x + p1 * c.x;
                o.y += p0 * a.y + p1 * c.y;
                o.z += p0 * a.z + p1 * c.z;
                o.w += p0 * a.w + p1 * c.w;
                o4[i] = o;
            }
        }
        float inv = 1.f / l;
        float* op = attnout + ((size_t)(b * NN + tid)) * CC + h * 32;
        #pragma unroll
        for (int i = 0; i < 8; i++) {
            float4 o = o4[i];
            *(float4*)(op + i * 4) = make_float4(o.x * inv, o.y * inv, o.z * inv, o.w * inv);
        }
    }
}

// ---------------- host: tensormap encode --------------------------------------
typedef CUresult (*PFN_encodeTiled)(
    CUtensorMap*, CUtensorMapDataType, cuuint32_t, void*,
    const cuuint64_t*, const cuuint64_t*, const cuuint32_t*, const cuuint32_t*,
    CUtensorMapInterleave, CUtensorMapSwizzle, CUtensorMapL2promotion,
    CUtensorMapFloatOOBfill);

static void encode_2d(PFN_encodeTiled enc, CUtensorMap* tm, void* base,
                      uint64_t rows, uint64_t cols, uint32_t box_rows) {
    cuuint64_t dims[2]    = { cols, rows };
    cuuint64_t strides[1] = { cols * 4 };
    cuuint32_t box[2]     = { 32, box_rows };   // 32 f32 = 128B (SW128 limit)
    cuuint32_t estr[2]    = { 1, 1 };
    enc(tm, CU_TENSOR_MAP_DATA_TYPE_FLOAT32, 2, base, dims, strides, box, estr,
        CU_TENSOR_MAP_INTERLEAVE_NONE, CU_TENSOR_MAP_SWIZZLE_128B,
        CU_TENSOR_MAP_L2_PROMOTION_L2_128B, CU_TENSOR_MAP_FLOAT_OOB_FILL_NONE);
}

// ---------------- launch ------------------------------------------------------
extern "C" void kernel_launch(void* const* d_in, const int* in_sizes, int n_in,
                              void* d_out, int out_size) {
    const float* x      = (const float*)d_in[0];
    const float* W_qkv  = (const float*)d_in[1];
    const float* b_qkv  = (const float*)d_in[2];
    const float* W_proj = (const float*)d_in[3];
    const float* b_proj = (const float*)d_in[4];
    const float* W1     = (const float*)d_in[5];
    const float* b1     = (const float*)d_in[6];
    const float* W2     = (const float*)d_in[7];
    const float* b2     = (const float*)d_in[8];
    const float* sa_w   = (const float*)d_in[9];
    const float* sa_b   = (const float*)d_in[10];
    const float* alpha1 = (const float*)d_in[11];
    const float* gamma1 = (const float*)d_in[12];
    const float* beta1  = (const float*)d_in[13];
    const float* rm1    = (const float*)d_in[14];
    const float* rv1    = (const float*)d_in[15];
    const float* alpha2 = (const float*)d_in[16];
    const float* gamma2 = (const float*)d_in[17];
    const float* beta2  = (const float*)d_in[18];
    const float* rm2    = (const float*)d_in[19];
    const float* rv2    = (const float*)d_in[20];
    float* out = (float*)d_out;

    float *t, *qkv, *attn, *t1, *hbuf, *wqkvT, *wprojT, *w1T, *w2T;
    cudaGetSymbolAddress((void**)&t,      g_t);
    cudaGetSymbolAddress((void**)&qkv,    g_qkv);
    cudaGetSymbolAddress((void**)&attn,   g_attn);
    cudaGetSymbolAddress((void**)&t1,     g_t1);
    cudaGetSymbolAddress((void**)&hbuf,   g_h);
    cudaGetSymbolAddress((void**)&wqkvT,  g_wqkvT);
    cudaGetSymbolAddress((void**)&wprojT, g_wprojT);
    cudaGetSymbolAddress((void**)&w1T,    g_w1T);
    cudaGetSymbolAddress((void**)&w2T,    g_w2T);

    void* fn = nullptr;
    cudaDriverEntryPointQueryResult qres;
    cudaGetDriverEntryPoint("cuTensorMapEncodeTiled", &fn, cudaEnableDefault, &qres);
    PFN_encodeTiled enc = (PFN_encodeTiled)fn;

    CUtensorMap tm_t, tm_wqkv, tm_attn, tm_wproj, tm_t1, tm_w1, tm_h, tm_w2;
    encode_2d(enc, &tm_t,     t,      MM,   256,  128);
    encode_2d(enc, &tm_wqkv,  wqkvT,  768,  256,  128);
    encode_2d(enc, &tm_attn,  attn,   MM,   256,  128);
    encode_2d(enc, &tm_wproj, wprojT, 256,  256,  128);
    encode_2d(enc, &tm_t1,    t1,     MM,   256,  128);
    encode_2d(enc, &tm_w1,    w1T,    CMID, 256,  128);
    encode_2d(enc, &tm_h,     hbuf,   MM,   CMID, 128);
    encode_2d(enc, &tm_w2,    w2T,    256,  CMID, 256);

    const int GEMM_SMEM  = 1024 + 2 * 32768;   // 66560
    const int GEMMW_SMEM = 1024 + 2 * 49152;   // 99328
    cudaFuncSetAttribute(k_tgemm,   cudaFuncAttributeMaxDynamicSharedMemorySize, GEMM_SMEM);
    cudaFuncSetAttribute(k_tgemm_w, cudaFuncAttributeMaxDynamicSharedMemorySize, GEMMW_SMEM);
    cudaFuncSetAttribute(k_attn,    cudaFuncAttributeMaxDynamicSharedMemorySize, 2 * NN * 32 * 4);

    dim3 tb(32, 8);
    k_wt<<<dim3(768 / 32, 256 / 32), tb>>>(W_qkv, wqkvT, 256, 768);
    k_wt<<<dim3(256 / 32, 256 / 32), tb>>>(W_proj, wprojT, 256, 256);
    k_wt<<<dim3(CMID / 32, 256 / 32), tb>>>(W1, w1T, 256, CMID);
    k_wt<<<dim3(256 / 32, CMID / 32), tb>>>(W2, w2T, CMID, 256);
    k_in_transpose<<<dim3(7, 8, BB), tb>>>(x, t);
    // QKV
    k_tgemm<<<dim3(768 / 128, MM / 128), 256, GEMM_SMEM>>>(tm_t, tm_wqkv, b_qkv, qkv,
        768, 256, 0, nullptr, nullptr, nullptr, nullptr, nullptr, nullptr, nullptr, nullptr);
    k_attn<<<dim3(8, BB), 256, 2 * NN * 32 * 4>>>(qkv, attn);
    // proj + residual + repbn1
    k_tgemm<<<dim3(256 / 128, MM / 128), 256, GEMM_SMEM>>>(tm_attn, tm_wproj, b_proj, t1,
        256, 256, 1, t, gamma1, beta1, rm1, rv1, alpha1, nullptr, nullptr);
    // FFN1 + SpatialSILU
    k_tgemm<<<dim3(CMID / 128, MM / 128), 256, GEMM_SMEM>>>(tm_t1, tm_w1, b1, hbuf,
        CMID, 256, 2, nullptr, nullptr, nullptr, nullptr, nullptr, nullptr, sa_w, sa_b);
    // FFN2 (wide) + residual + repbn2 -> [B,C,N]
    k_tgemm_w<<<MM / 128, 256, GEMMW_SMEM>>>(tm_h, tm_w2, b2, out,
        CMID, t1, gamma2, beta2, rm2, rv2, alpha2);
}

// round 11
// speedup vs baseline: 2.8973x; 1.4803x over previous
#include <cuda_runtime.h>
#include <cuda.h>
#include <cstdint>
#include <math.h>

#define BB 256
#define CC 256
#define NN 196
#define MM (BB*NN)        // 50176
#define CMID 2048
#define EPSL 1e-5f

#if defined(__CUDA_ARCH_FEAT_SM103_ALL) || defined(__CUDA_ARCH_FEAT_SM100_ALL) || defined(__CUDA_ARCH_FEAT_SM101_ALL)
#define TC_OK 1
#else
#define TC_OK 0
#endif

// ---------------- scratch (device globals) -----------------------------------
__device__ float g_t   [(size_t)MM*CC];
__device__ float g_qkv [(size_t)MM*3*CC];
__device__ float g_attn[(size_t)MM*CC];
__device__ float g_t1  [(size_t)MM*CC];
__device__ float g_h   [(size_t)MM*CMID];
__device__ float g_wqkvT[(size_t)3*CC*CC];   // [768,256]
__device__ float g_wprojT[(size_t)CC*CC];    // [256,256]
__device__ float g_w1T  [(size_t)CMID*CC];   // [2048,256]
__device__ float g_w2T  [(size_t)CC*CMID];   // [256,2048]

// ---------------- PTX helpers -------------------------------------------------
__device__ __forceinline__ uint32_t smem_u32(const void* p) {
    uint32_t a;
    asm("{ .reg .u64 t; cvta.to.shared.u64 t, %1; cvt.u32.u64 %0, t; }" : "=r"(a) : "l"(p));
    return a;
}

#define MBAR_INIT(addr, cnt) \
    asm volatile("mbarrier.init.shared.b64 [%0], %1;" :: "r"(addr), "r"(cnt) : "memory")

#define MBAR_WAIT(addr, parity) do {                                              \
    uint32_t _m = (addr); uint32_t _p = (parity); uint32_t _d;                    \
    asm volatile("{\n\t.reg .pred p;\n\t"                                         \
        "mbarrier.try_wait.parity.acquire.cta.shared::cta.b64 p, [%1], %2;\n\t"   \
        "selp.b32 %0, 1, 0, p;\n\t}" : "=r"(_d) : "r"(_m), "r"(_p) : "memory");   \
    if (!_d) {                                                                     \
        asm volatile("{\n\t.reg .pred P1;\n\t"                                     \
            "W_%=:\n\t"                                                            \
            "mbarrier.try_wait.parity.acquire.cta.shared::cta.b64 P1, [%0], %1, 0x989680;\n\t" \
            "@P1 bra.uni D_%=;\n\t"                                                \
            "bra.uni W_%=;\n\t"                                                    \
            "D_%=:\n\t}" :: "r"(_m), "r"(_p) : "memory");                          \
    } } while (0)

#if TC_OK
#define MBAR_EXPECT(mbar, bytes) \
    asm volatile("mbarrier.arrive.expect_tx.shared.b64 _, [%0], %1;" \
                 :: "r"(mbar), "r"(bytes) : "memory")

#define TMA_LD2D(smem, tmapp, c0, c1, mbar) \
    asm volatile("cp.async.bulk.tensor.2d.shared::cta.global.tile.mbarrier::complete_tx::bytes " \
                 "[%0], [%1, {%2, %3}], [%4];" \
                 :: "r"(smem), "l"(tmapp), "r"(c0), "r"(c1), "r"(mbar) : "memory")

__device__ __forceinline__ void mma_tf32(uint32_t d, uint64_t ad, uint64_t bd,
                                         uint32_t idesc, bool acc) {
    uint32_t e = acc ? 1u : 0u;
    asm volatile(
        "{\n\t.reg .pred p;\n\tsetp.ne.u32 p, %5, 0;\n\t"
        "tcgen05.mma.cta_group::1.kind::tf32 [%0], %1, %2, %3, {%4, %4, %4, %4}, p;\n\t}"
        :: "r"(d), "l"(ad), "l"(bd), "r"(idesc), "r"(0u), "r"(e) : "memory");
}

__device__ __forceinline__ void mma_tf32_ts(uint32_t d, uint32_t a_tm, uint64_t bd,
                                            uint32_t idesc, bool acc) {
    uint32_t e = acc ? 1u : 0u;
    asm volatile(
        "{\n\t.reg .pred p;\n\tsetp.ne.u32 p, %5, 0;\n\t"
        "tcgen05.mma.cta_group::1.kind::tf32 [%0], [%1], %2, %3, {%4, %4, %4, %4}, p;\n\t}"
        :: "r"(d), "r"(a_tm), "l"(bd), "r"(idesc), "r"(0u), "r"(e) : "memory");
}

#define LDTM_X32(r, addr)                                                         \
    asm volatile("tcgen05.ld.sync.aligned.32x32b.x32.b32 "                        \
        "{%0, %1, %2, %3, %4, %5, %6, %7, %8, %9, %10, %11, %12, %13, %14, %15, " \
        " %16, %17, %18, %19, %20, %21, %22, %23, %24, %25, %26, %27, %28, %29, %30, %31}, [%32];" \
        : "=r"((r)[0]), "=r"((r)[1]), "=r"((r)[2]), "=r"((r)[3]),                 \
          "=r"((r)[4]), "=r"((r)[5]), "=r"((r)[6]), "=r"((r)[7]),                 \
          "=r"((r)[8]), "=r"((r)[9]), "=r"((r)[10]), "=r"((r)[11]),               \
          "=r"((r)[12]), "=r"((r)[13]), "=r"((r)[14]), "=r"((r)[15]),             \
          "=r"((r)[16]), "=r"((r)[17]), "=r"((r)[18]), "=r"((r)[19]),             \
          "=r"((r)[20]), "=r"((r)[21]), "=r"((r)[22]), "=r"((r)[23]),             \
          "=r"((r)[24]), "=r"((r)[25]), "=r"((r)[26]), "=r"((r)[27]),             \
          "=r"((r)[28]), "=r"((r)[29]), "=r"((r)[30]), "=r"((r)[31])              \
        : "r"(addr))

#define STTM_X32(addr, r)                                                         \
    asm volatile("tcgen05.st.sync.aligned.32x32b.x32.b32 [%0], "                  \
        "{%1, %2, %3, %4, %5, %6, %7, %8, %9, %10, %11, %12, %13, %14, %15, %16, "\
        " %17, %18, %19, %20, %21, %22, %23, %24, %25, %26, %27, %28, %29, %30, %31, %32};" \
        :: "r"(addr),                                                             \
           "r"((r)[0]), "r"((r)[1]), "r"((r)[2]), "r"((r)[3]),                    \
           "r"((r)[4]), "r"((r)[5]), "r"((r)[6]), "r"((r)[7]),                    \
           "r"((r)[8]), "r"((r)[9]), "r"((r)[10]), "r"((r)[11]),                  \
           "r"((r)[12]), "r"((r)[13]), "r"((r)[14]), "r"((r)[15]),                \
           "r"((r)[16]), "r"((r)[17]), "r"((r)[18]), "r"((r)[19]),                \
           "r"((r)[20]), "r"((r)[21]), "r"((r)[22]), "r"((r)[23]),                \
           "r"((r)[24]), "r"((r)[25]), "r"((r)[26]), "r"((r)[27]),                \
           "r"((r)[28]), "r"((r)[29]), "r"((r)[30]), "r"((r)[31])                 \
        : "memory")
#endif

static constexpr uint64_t DESC_BASE =
    (uint64_t(2) << 61) | (uint64_t(1) << 46) | (uint64_t(64) << 32) | (uint64_t(1) << 16);

// ---------------- transpose x [B][C][N] -> t [B*N][C] -------------------------
__global__ void k_in_transpose(const float* __restrict__ x, float* __restrict__ t) {
    __shared__ float tile[32][33];
    int b = blockIdx.z;
    int n0 = blockIdx.x * 32, c0 = blockIdx.y * 32;
    int tx = threadIdx.x, ty = threadIdx.y;
    const float* xb = x + (size_t)b * CC * NN;
    #pragma unroll
    for (int j = 0; j < 32; j += 8) {
        int c = c0 + ty + j, n = n0 + tx;
        if (n < NN) tile[ty + j][tx] = xb[(size_t)c * NN + n];
    }
    __syncthreads();
    #pragma unroll
    for (int j = 0; j < 32; j += 8) {
        int n = n0 + ty + j, c = c0 + tx;
        if (n < NN) t[((size_t)b * NN + n) * CC + c] = tile[tx][ty + j];
    }
}

// ---------------- weight transpose W[R,C] -> Wt[C,R] --------------------------
__global__ void k_wt(const float* __restrict__ W, float* __restrict__ Wt, int R, int C) {
    __shared__ float tile[32][33];
    int c0 = blockIdx.x * 32, r0 = blockIdx.y * 32;
    int tx = threadIdx.x, ty = threadIdx.y;
    #pragma unroll
    for (int j = 0; j < 32; j += 8)
        tile[ty + j][tx] = W[(size_t)(r0 + ty + j) * C + c0 + tx];
    __syncthreads();
    #pragma unroll
    for (int j = 0; j < 32; j += 8)
        Wt[(size_t)(c0 + ty + j) * R + r0 + tx] = tile[tx][ty + j];
}

// ---------------- TMA tcgen05 tf32 GEMM 128x128: out = A @ Bt^T + epilogue ----
// epi 0: +bias ; epi 1: +bias, repbn(res+v) ; epi 2: +bias, SpatialSILU
__global__ __launch_bounds__(256)
void k_tgemm(const __grid_constant__ CUtensorMap tmA,
             const __grid_constant__ CUtensorMap tmB,
             const float* __restrict__ bias, float* __restrict__ out,
             int N, int K, int epi,
             const float* __restrict__ res,
             const float* __restrict__ gam, const float* __restrict__ bet,
             const float* __restrict__ rm,  const float* __restrict__ rv,
             const float* __restrict__ alpha,
             const float* __restrict__ saw, const float* __restrict__ sab)
{
#if TC_OK
    extern __shared__ char smem_raw[];
    __shared__ uint64_t s_mbar[5];   // full0, full1, empty0, empty1, done
    __shared__ uint32_t s_tmem;

    uint32_t sb_raw = smem_u32(smem_raw);
    uint32_t tbase = (sb_raw + 1023u) & ~1023u;
    char* tptr = smem_raw + (tbase - sb_raw);

    int tid = threadIdx.x;
    int wid = tid >> 5, lid = tid & 31;
    int m0 = blockIdx.y * 128, n0 = blockIdx.x * 128;

    if (wid == 0)
        asm volatile("tcgen05.alloc.cta_group::1.sync.aligned.shared::cta.b32 [%0], %1;"
                     :: "r"(smem_u32(&s_tmem)), "r"(128) : "memory");
    if (tid == 0)
        for (int i = 0; i < 5; i++) MBAR_INIT(smem_u32(&s_mbar[i]), 1);
    __syncthreads();
    uint32_t tmem = s_tmem;
    if (wid == 0)
        asm volatile("tcgen05.relinquish_alloc_permit.cta_group::1.sync.aligned;");

    const uint32_t IDESC = (1u << 4) | (2u << 7) | (2u << 10) | (16u << 17) | (8u << 24);
    const int KC = K >> 5;

    if (tid == 0) {
        uint32_t full[2]  = { smem_u32(&s_mbar[0]), smem_u32(&s_mbar[1]) };
        uint32_t empty[2] = { smem_u32(&s_mbar[2]), smem_u32(&s_mbar[3]) };
        int phf[2] = {0, 0}, phe[2] = {0, 0};
        #pragma unroll
        for (int p = 0; p < 2; p++) {
            uint32_t sA = tbase + p * 32768, sB = sA + 16384;
            MBAR_EXPECT(full[p], 32768);
            TMA_LD2D(sA, &tmA, p * 32, m0, full[p]);
            TMA_LD2D(sB, &tmB, p * 32, n0, full[p]);
        }
        for (int kc = 0; kc < KC; kc++) {
            int buf = kc & 1;
            uint32_t sA = tbase + buf * 32768, sB = sA + 16384;
            MBAR_WAIT(full[buf], phf[buf]); phf[buf] ^= 1;
            uint64_t ad = DESC_BASE | ((uint64_t)(sA >> 4) & 0x3FFF);
            uint64_t bd = DESC_BASE | ((uint64_t)(sB >> 4) & 0x3FFF);
            #pragma unroll
            for (int s = 0; s < 4; s++)
                mma_tf32(tmem, ad + s * 2, bd + s * 2, IDESC, (kc > 0) || (s > 0));
            asm volatile(
                "tcgen05.commit.cta_group::1.mbarrier::arrive::one.shared::cluster.b64 [%0];"
                :: "r"(empty[buf]) : "memory");
            if (kc + 2 < KC) {
                MBAR_WAIT(empty[buf], phe[buf]); phe[buf] ^= 1;
                MBAR_EXPECT(full[buf], 32768);
                TMA_LD2D(sA, &tmA, (kc + 2) * 32, m0, full[buf]);
                TMA_LD2D(sB, &tmB, (kc + 2) * 32, n0, full[buf]);
            }
        }
        asm volatile(
            "tcgen05.commit.cta_group::1.mbarrier::arrive::one.shared::cluster.b64 [%0];"
            :: "r"(smem_u32(&s_mbar[4])) : "memory");
    }
    MBAR_WAIT(smem_u32(&s_mbar[4]), 0);
    asm volatile("tcgen05.fence::after_thread_sync;" ::: "memory");
    __syncthreads();

    // ---- 8-warp coalesced epilogue ----
    {
        int sub = wid & 3, half = wid >> 2;
        float* spatch = (float*)tptr + wid * (32 * 33);
        int mrow = m0 + sub * 32;
        float alphav = (epi == 1) ? alpha[0] : 0.f;
        #pragma unroll
        for (int cb = 0; cb < 2; cb++) {
            int c0 = half * 64 + cb * 32;
            uint32_t r[32];
            LDTM_X32(r, tmem + c0);
            asm volatile("tcgen05.wait::ld.sync.aligned;" ::: "memory");
            #pragma unroll
            for (int j = 0; j < 32; j++) spatch[lid * 33 + j] = __uint_as_float(r[j]);
            __syncwarp();
            #pragma unroll
            for (int i = 0; i < 8; i++) {
                int rr = i * 4 + (lid >> 3);
                int c4 = (lid & 7) * 4;
                int m = mrow + rr;
                int n = n0 + c0 + c4;
                float vv[4];
                #pragma unroll
                for (int e = 0; e < 4; e++) vv[e] = spatch[rr * 33 + c4 + e];
                float4 bb = *(const float4*)(bias + n);
                vv[0] += bb.x; vv[1] += bb.y; vv[2] += bb.z; vv[3] += bb.w;
                if (epi == 1) {
                    float4 r4 = *(const float4*)(res + (size_t)m * N + n);
                    float4 g4 = *(const float4*)(gam + n);
                    float4 b4 = *(const float4*)(bet + n);
                    float4 u4 = *(const float4*)(rm + n);
                    float4 s4 = *(const float4*)(rv + n);
                    float y;
                    y = r4.x + vv[0]; vv[0] = (y - u4.x) * (g4.x * rsqrtf(s4.x + EPSL)) + b4.x + alphav * y;
                    y = r4.y + vv[1]; vv[1] = (y - u4.y) * (g4.y * rsqrtf(s4.y + EPSL)) + b4.y + alphav * y;
                    y = r4.z + vv[2]; vv[2] = (y - u4.z) * (g4.z * rsqrtf(s4.z + EPSL)) + b4.z + alphav * y;
                    y = r4.w + vv[3]; vv[3] = (y - u4.w) * (g4.w * rsqrtf(s4.w + EPSL)) + b4.w + alphav * y;
                } else if (epi == 2) {
                    int bidx = m / NN;
                    float sw_ = saw[bidx], sbv = sab[bidx];
                    #pragma unroll
                    for (int e = 0; e < 4; e++) {
                        float w = sw_ * vv[e] + sbv;
                        vv[e] = vv[e] / (1.f + __expf(-w * vv[e]));
                    }
                }
                *(float4*)(out + (size_t)m * N + n) = make_float4(vv[0], vv[1], vv[2], vv[3]);
            }
            __syncwarp();
        }
    }
    __syncthreads();
    if (tid == 0)
        for (int i = 0; i < 5; i++)
            asm volatile("mbarrier.inval.shared.b64 [%0];" :: "r"(smem_u32(&s_mbar[i])) : "memory");
    __syncthreads();
    if (wid == 0)
        asm volatile("tcgen05.dealloc.cta_group::1.sync.aligned.b32 %0, %1;"
                     :: "r"(tmem), "r"(128));
#endif
}

// ---------------- TMA wide GEMM 128x256 (FFN2): single hbuf read, BCN out -----
__global__ __launch_bounds__(256)
void k_tgemm_w(const __grid_constant__ CUtensorMap tmA,
               const __grid_constant__ CUtensorMap tmB,
               const float* __restrict__ bias, float* __restrict__ out,
               int K,
               const float* __restrict__ res,
               const float* __restrict__ gam, const float* __restrict__ bet,
               const float* __restrict__ rm,  const float* __restrict__ rv,
               const float* __restrict__ alpha)
{
#if TC_OK
    extern __shared__ char smem_raw[];
    __shared__ uint64_t s_mbar[5];
    __shared__ uint32_t s_tmem;

    uint32_t sb_raw = smem_u32(smem_raw);
    uint32_t tbase = (sb_raw + 1023u) & ~1023u;
    char* tptr = smem_raw + (tbase - sb_raw);

    int tid = threadIdx.x;
    int wid = tid >> 5, lid = tid & 31;
    int m0 = blockIdx.x * 128;
    const int N = 256;

    if (wid == 0)
        asm volatile("tcgen05.alloc.cta_group::1.sync.aligned.shared::cta.b32 [%0], %1;"
                     :: "r"(smem_u32(&s_tmem)), "r"(256) : "memory");
    if (tid == 0)
        for (int i = 0; i < 5; i++) MBAR_INIT(smem_u32(&s_mbar[i]), 1);
    __syncthreads();
    uint32_t tmem = s_tmem;
    if (wid == 0)
        asm volatile("tcgen05.relinquish_alloc_permit.cta_group::1.sync.aligned;");

    const uint32_t IDESC = (1u << 4) | (2u << 7) | (2u << 10) | (32u << 17) | (8u << 24);
    const int KC = K >> 5;

    if (tid == 0) {
        uint32_t full[2]  = { smem_u32(&s_mbar[0]), smem_u32(&s_mbar[1]) };
        uint32_t empty[2] = { smem_u32(&s_mbar[2]), smem_u32(&s_mbar[3]) };
        int phf[2] = {0, 0}, phe[2] = {0, 0};
        #pragma unroll
        for (int p = 0; p < 2; p++) {
            uint32_t sA = tbase + p * 49152, sB = sA + 16384;
            MBAR_EXPECT(full[p], 49152);
            TMA_LD2D(sA, &tmA, p * 32, m0, full[p]);
            TMA_LD2D(sB, &tmB, p * 32, 0, full[p]);
        }
        for (int kc = 0; kc < KC; kc++) {
            int buf = kc & 1;
            uint32_t sA = tbase + buf * 49152, sB = sA + 16384;
            MBAR_WAIT(full[buf], phf[buf]); phf[buf] ^= 1;
            uint64_t ad = DESC_BASE | ((uint64_t)(sA >> 4) & 0x3FFF);
            uint64_t bd = DESC_BASE | ((uint64_t)(sB >> 4) & 0x3FFF);
            #pragma unroll
            for (int s = 0; s < 4; s++)
                mma_tf32(tmem, ad + s * 2, bd + s * 2, IDESC, (kc > 0) || (s > 0));
            asm volatile(
                "tcgen05.commit.cta_group::1.mbarrier::arrive::one.shared::cluster.b64 [%0];"
                :: "r"(empty[buf]) : "memory");
            if (kc + 2 < KC) {
                MBAR_WAIT(empty[buf], phe[buf]); phe[buf] ^= 1;
                MBAR_EXPECT(full[buf], 49152);
                TMA_LD2D(sA, &tmA, (kc + 2) * 32, m0, full[buf]);
                TMA_LD2D(sB, &tmB, (kc + 2) * 32, 0, full[buf]);
            }
        }
        asm volatile(
            "tcgen05.commit.cta_group::1.mbarrier::arrive::one.shared::cluster.b64 [%0];"
            :: "r"(smem_u32(&s_mbar[4])) : "memory");
    }
    MBAR_WAIT(smem_u32(&s_mbar[4]), 0);
    asm volatile("tcgen05.fence::after_thread_sync;" ::: "memory");
    __syncthreads();

    // 8-warp epilogue -> [B,C,N]
    {
        int sub = wid & 3, half = wid >> 2;
        float* spatch = (float*)tptr + wid * (32 * 33);
        int mrow = m0 + sub * 32;
        float alphav = alpha[0];
        int m_out = mrow + lid;
        int b_o = m_out / NN, nsp = m_out % NN;
        size_t obase = (size_t)b_o * CC * NN + nsp;
        #pragma unroll
        for (int cb = 0; cb < 4; cb++) {
            int c0 = half * 128 + cb * 32;
            uint32_t r[32];
            LDTM_X32(r, tmem + c0);
            asm volatile("tcgen05.wait::ld.sync.aligned;" ::: "memory");
            #pragma unroll
            for (int j = 0; j < 32; j++) spatch[lid * 33 + j] = __uint_as_float(r[j]);
            __syncwarp();
            #pragma unroll
            for (int i = 0; i < 8; i++) {
                int rr = i * 4 + (lid >> 3);
                int c4 = (lid & 7) * 4;
                int m = mrow + rr;
                int n = c0 + c4;
                float vv[4];
                #pragma unroll
                for (int e = 0; e < 4; e++) vv[e] = spatch[rr * 33 + c4 + e];
                float4 bb = *(const float4*)(bias + n);
                float4 r4 = *(const float4*)(res + (size_t)m * N + n);
                float4 g4 = *(const float4*)(gam + n);
                float4 b4 = *(const float4*)(bet + n);
                float4 u4 = *(const float4*)(rm + n);
                float4 s4 = *(const float4*)(rv + n);
                float y;
                y = r4.x + vv[0] + bb.x; vv[0] = (y - u4.x) * (g4.x * rsqrtf(s4.x + EPSL)) + b4.x + alphav * y;
                y = r4.y + vv[1] + bb.y; vv[1] = (y - u4.y) * (g4.y * rsqrtf(s4.y + EPSL)) + b4.y + alphav * y;
                y = r4.z + vv[2] + bb.z; vv[2] = (y - u4.z) * (g4.z * rsqrtf(s4.z + EPSL)) + b4.z + alphav * y;
                y = r4.w + vv[3] + bb.w; vv[3] = (y - u4.w) * (g4.w * rsqrtf(s4.w + EPSL)) + b4.w + alphav * y;
                #pragma unroll
                for (int e = 0; e < 4; e++) spatch[rr * 33 + c4 + e] = vv[e];
            }
            __syncwarp();
            #pragma unroll
            for (int cc = 0; cc < 32; cc++)
                out[obase + (size_t)(c0 + cc) * NN] = spatch[lid * 33 + cc];
            __syncwarp();
        }
    }
    __syncthreads();
    if (tid == 0)
        for (int i = 0; i < 5; i++)
            asm volatile("mbarrier.inval.shared.b64 [%0];" :: "r"(smem_u32(&s_mbar[i])) : "memory");
    __syncthreads();
    if (wid == 0)
        asm volatile("tcgen05.dealloc.cta_group::1.sync.aligned.b32 %0, %1;"
                     :: "r"(tmem), "r"(256));
#endif
}

// ---------------- flash attention on tcgen05: block = (h, b) ------------------
// smem: Q 32KB @0 (256 rows), K 28KB @32768 (224 rows), V^T 28KB @61440 (blocked atom)
__global__ __launch_bounds__(256)
void k_fattn(const __grid_constant__ CUtensorMap tmQKV,
             const float* __restrict__ qkv, float* __restrict__ attnout)
{
#if TC_OK
    extern __shared__ char smem_raw[];
    __shared__ uint64_t s_mbar[3];   // tma_full, done1, done2
    __shared__ uint32_t s_tmem;

    uint32_t sb_raw = smem_u32(smem_raw);
    uint32_t tbase = (sb_raw + 1023u) & ~1023u;
    char* tptr = smem_raw + (tbase - sb_raw);

    int tid = threadIdx.x, wid = tid >> 5, lid = tid & 31;
    int h = blockIdx.x, b = blockIdx.y;
    const uint32_t QOFF = 0, KOFF = 32768, VOFF = 61440;

    if (wid == 0)
        asm volatile("tcgen05.alloc.cta_group::1.sync.aligned.shared::cta.b32 [%0], %1;"
                     :: "r"(smem_u32(&s_tmem)), "r"(512) : "memory");
    if (tid == 0)
        for (int i = 0; i < 3; i++) MBAR_INIT(smem_u32(&s_mbar[i]), 1);
    __syncthreads();
    uint32_t tmem = s_tmem;
    if (wid == 0)
        asm volatile("tcgen05.relinquish_alloc_permit.cta_group::1.sync.aligned;");

    // TMA Q, K (196 rows each); V transposed via SIMT
    if (tid == 0) {
        MBAR_EXPECT(smem_u32(&s_mbar[0]), 2 * 196 * 128);
        TMA_LD2D(tbase + QOFF, &tmQKV, h * 32, b * 196, smem_u32(&s_mbar[0]));
        TMA_LD2D(tbase + KOFF, &tmQKV, 256 + h * 32, b * 196, smem_u32(&s_mbar[0]));
    }

    // zero V^T region (pad rows must be finite)
    for (int i = tid; i < 1792; i += 256)
        ((float4*)(tptr + VOFF))[i] = make_float4(0.f, 0.f, 0.f, 0.f);
    __syncthreads();
    // V^T blocked-atom store: atom = 8 rows x 32 floats; 32 d-rows x 224 n-cols
    {
        size_t vbase = (size_t)b * 196 * 768 + 512 + (size_t)h * 32;
        for (int idx = tid; idx < 196 * 32; idx += 256) {
            int m = idx >> 5, d = idx & 31;
            float v = qkv[vbase + (size_t)m * 768 + d];
            int atom = (d >> 3) + (m >> 5) * 4;
            uint32_t bo = atom * 1024 + (d & 7) * 128 + (m & 31) * 4;
            uint32_t sw = bo ^ ((bo >> 3) & 0x70);
            *(float*)(tptr + VOFF + sw) = v;
        }
    }
    __syncthreads();

    const uint32_t IDESC1 = (1u << 4) | (2u << 7) | (2u << 10) | (28u << 17) | (8u << 24); // N=224
    const uint32_t IDESC2 = (1u << 4) | (2u << 7) | (2u << 10) | (4u << 17)  | (8u << 24); // N=32

    // MMA1: S = Q @ K^T  (two M=128 tiles)
    if (tid == 0) {
        MBAR_WAIT(smem_u32(&s_mbar[0]), 0);
        asm volatile("fence.proxy.async.shared::cta;" ::: "memory");  // V^T generic writes
        uint64_t qd0 = DESC_BASE | ((uint64_t)((tbase + QOFF) >> 4) & 0x3FFF);
        uint64_t qd1 = DESC_BASE | ((uint64_t)((tbase + QOFF + 16384) >> 4) & 0x3FFF);
        uint64_t kd  = DESC_BASE | ((uint64_t)((tbase + KOFF) >> 4) & 0x3FFF);
        #pragma unroll
        for (int s = 0; s < 4; s++) mma_tf32(tmem,       qd0 + s * 2, kd + s * 2, IDESC1, s > 0);
        #pragma unroll
        for (int s = 0; s < 4; s++) mma_tf32(tmem + 224, qd1 + s * 2, kd + s * 2, IDESC1, s > 0);
        asm volatile(
            "tcgen05.commit.cta_group::1.mbarrier::arrive::one.shared::cluster.b64 [%0];"
            :: "r"(smem_u32(&s_mbar[1])) : "memory");
    }
    MBAR_WAIT(smem_u32(&s_mbar[1]), 0);
    asm volatile("tcgen05.fence::after_thread_sync;" ::: "memory");

    // softmax in place: warp (tile = wid>>2, sub = wid&3)
    int sub = wid & 3, tile = wid >> 2;
    uint32_t Sbase = tmem + tile * 224;
    uint32_t stoff = (uint32_t)sub << 21;
    float l = 0.f;
    const float SC = 0.17677669529663687f;
    #pragma unroll
    for (int cb = 0; cb < 7; cb++) {
        uint32_t r[32];
        LDTM_X32(r, Sbase + cb * 32);
        asm volatile("tcgen05.wait::ld.sync.aligned;" ::: "memory");
        int vlim = (cb == 6) ? 4 : 32;   // col cb*32+j valid if < 196
        #pragma unroll
        for (int j = 0; j < 32; j++) {
            float p = 0.f;
            if (j < vlim) { p = __expf(__uint_as_float(r[j]) * SC); l += p; }
            r[j] = __float_as_uint(p);
        }
        STTM_X32(Sbase + cb * 32 + stoff, r);
        asm volatile("tcgen05.wait::st.sync.aligned;" ::: "memory");
    }
    asm volatile("tcgen05.fence::before_thread_sync;" ::: "memory");
    __syncthreads();

    // MMA2: O = P @ V  (TS: A = P in TMEM, B = V^T blocked atom, K=224)
    if (tid == 0) {
        asm volatile("tcgen05.fence::after_thread_sync;" ::: "memory");
        uint64_t vd = DESC_BASE | ((uint64_t)((tbase + VOFF) >> 4) & 0x3FFF);
        #pragma unroll
        for (int t = 0; t < 2; t++) {
            #pragma unroll
            for (int c = 0; c < 28; c++) {
                uint64_t bd = vd + (uint64_t)((c >> 2) * 256 + (c & 3) * 2);
                mma_tf32_ts(tmem + 448 + t * 32, tmem + t * 224 + c * 8, bd, IDESC2, c > 0);
            }
        }
        asm volatile(
            "tcgen05.commit.cta_group::1.mbarrier::arrive::one.shared::cluster.b64 [%0];"
            :: "r"(smem_u32(&s_mbar[2])) : "memory");
    }
    MBAR_WAIT(smem_u32(&s_mbar[2]), 0);
    asm volatile("tcgen05.fence::after_thread_sync;" ::: "memory");

    // drain O: warp reads its 32 rows x 32 d-cols, scale 1/l
    {
        uint32_t r[32];
        LDTM_X32(r, tmem + 448 + tile * 32);
        asm volatile("tcgen05.wait::ld.sync.aligned;" ::: "memory");
        int row = tile * 128 + sub * 32 + lid;
        if (row < 196) {
            float inv = 1.f / l;
            float* op = attnout + ((size_t)(b * NN + row)) * CC + h * 32;
            #pragma unroll
            for (int i = 0; i < 8; i++) {
                float4 o = make_float4(__uint_as_float(r[i*4+0]) * inv,
                                       __uint_as_float(r[i*4+1]) * inv,
                                       __uint_as_float(r[i*4+2]) * inv,
                                       __uint_as_float(r[i*4+3]) * inv);
                *(float4*)(op + i * 4) = o;
            }
        }
    }
    __syncthreads();
    if (tid == 0)
        for (int i = 0; i < 3; i++)
            asm volatile("mbarrier.inval.shared.b64 [%0];" :: "r"(smem_u32(&s_mbar[i])) : "memory");
    __syncthreads();
    if (wid == 0)
        asm volatile("tcgen05.dealloc.cta_group::1.sync.aligned.b32 %0, %1;"
                     :: "r"(tmem), "r"(512));
#endif
}

// ---------------- host: tensormap encode --------------------------------------
typedef CUresult (*PFN_encodeTiled)(
    CUtensorMap*, CUtensorMapDataType, cuuint32_t, void*,
    const cuuint64_t*, const cuuint64_t*, const cuuint32_t*, const cuuint32_t*,
    CUtensorMapInterleave, CUtensorMapSwizzle, CUtensorMapL2promotion,
    CUtensorMapFloatOOBfill);

static void encode_2d(PFN_encodeTiled enc, CUtensorMap* tm, void* base,
                      uint64_t rows, uint64_t cols, uint32_t box_rows) {
    cuuint64_t dims[2]    = { cols, rows };
    cuuint64_t strides[1] = { cols * 4 };
    cuuint32_t box[2]     = { 32, box_rows };   // 32 f32 = 128B (SW128 limit)
    cuuint32_t estr[2]    = { 1, 1 };
    enc(tm, CU_TENSOR_MAP_DATA_TYPE_FLOAT32, 2, base, dims, strides, box, estr,
        CU_TENSOR_MAP_INTERLEAVE_NONE, CU_TENSOR_MAP_SWIZZLE_128B,
        CU_TENSOR_MAP_L2_PROMOTION_L2_128B, CU_TENSOR_MAP_FLOAT_OOB_FILL_NONE);
}

// ---------------- launch ------------------------------------------------------
extern "C" void kernel_launch(void* const* d_in, const int* in_sizes, int n_in,
                              void* d_out, int out_size) {
    const float* x      = (const float*)d_in[0];
    const float* W_qkv  = (const float*)d_in[1];
    const float* b_qkv  = (const float*)d_in[2];
    const float* W_proj = (const float*)d_in[3];
    const float* b_proj = (const float*)d_in[4];
    const float* W1     = (const float*)d_in[5];
    const float* b1     = (const float*)d_in[6];
    const float* W2     = (const float*)d_in[7];
    const float* b2     = (const float*)d_in[8];
    const float* sa_w   = (const float*)d_in[9];
    const float* sa_b   = (const float*)d_in[10];
    const float* alpha1 = (const float*)d_in[11];
    const float* gamma1 = (const float*)d_in[12];
    const float* beta1  = (const float*)d_in[13];
    const float* rm1    = (const float*)d_in[14];
    const float* rv1    = (const float*)d_in[15];
    const float* alpha2 = (const float*)d_in[16];
    const float* gamma2 = (const float*)d_in[17];
    const float* beta2  = (const float*)d_in[18];
    const float* rm2    = (const float*)d_in[19];
    const float* rv2    = (const float*)d_in[20];
    float* out = (float*)d_out;

    float *t, *qkv, *attn, *t1, *hbuf, *wqkvT, *wprojT, *w1T, *w2T;
    cudaGetSymbolAddress((void**)&t,      g_t);
    cudaGetSymbolAddress((void**)&qkv,    g_qkv);
    cudaGetSymbolAddress((void**)&attn,   g_attn);
    cudaGetSymbolAddress((void**)&t1,     g_t1);
    cudaGetSymbolAddress((void**)&hbuf,   g_h);
    cudaGetSymbolAddress((void**)&wqkvT,  g_wqkvT);
    cudaGetSymbolAddress((void**)&wprojT, g_wprojT);
    cudaGetSymbolAddress((void**)&w1T,    g_w1T);
    cudaGetSymbolAddress((void**)&w2T,    g_w2T);

    void* fn = nullptr;
    cudaDriverEntryPointQueryResult qres;
    cudaGetDriverEntryPoint("cuTensorMapEncodeTiled", &fn, cudaEnableDefault, &qres);
    PFN_encodeTiled enc = (PFN_encodeTiled)fn;

    CUtensorMap tm_t, tm_wqkv, tm_attn, tm_wproj, tm_t1, tm_w1, tm_h, tm_w2, tm_qa;
    encode_2d(enc, &tm_t,     t,      MM,   256,  128);
    encode_2d(enc, &tm_wqkv,  wqkvT,  768,  256,  128);
    encode_2d(enc, &tm_attn,  attn,   MM,   256,  128);
    encode_2d(enc, &tm_wproj, wprojT, 256,  256,  128);
    encode_2d(enc, &tm_t1,    t1,     MM,   256,  128);
    encode_2d(enc, &tm_w1,    w1T,    CMID, 256,  128);
    encode_2d(enc, &tm_h,     hbuf,   MM,   CMID, 128);
    encode_2d(enc, &tm_w2,    w2T,    256,  CMID, 256);
    encode_2d(enc, &tm_qa,    qkv,    MM,   768,  196);

    const int GEMM_SMEM  = 1024 + 2 * 32768;   // 66560
    const int GEMMW_SMEM = 1024 + 2 * 49152;   // 99328
    const int FATT_SMEM  = 1024 + 32768 + 28672 + 28672;  // 91136
    cudaFuncSetAttribute(k_tgemm,   cudaFuncAttributeMaxDynamicSharedMemorySize, GEMM_SMEM);
    cudaFuncSetAttribute(k_tgemm_w, cudaFuncAttributeMaxDynamicSharedMemorySize, GEMMW_SMEM);
    cudaFuncSetAttribute(k_fattn,   cudaFuncAttributeMaxDynamicSharedMemorySize, FATT_SMEM);

    dim3 tb(32, 8);
    k_wt<<<dim3(768 / 32, 256 / 32), tb>>>(W_qkv, wqkvT, 256, 768);
    k_wt<<<dim3(256 / 32, 256 / 32), tb>>>(W_proj, wprojT, 256, 256);
    k_wt<<<dim3(CMID / 32, 256 / 32), tb>>>(W1, w1T, 256, CMID);
    k_wt<<<dim3(256 / 32, CMID / 32), tb>>>(W2, w2T, CMID, 256);
    k_in_transpose<<<dim3(7, 8, BB), tb>>>(x, t);
    // QKV
    k_tgemm<<<dim3(768 / 128, MM / 128), 256, GEMM_SMEM>>>(tm_t, tm_wqkv, b_qkv, qkv,
        768, 256, 0, nullptr, nullptr, nullptr, nullptr, nullptr, nullptr, nullptr, nullptr);
    // flash attention on tensor cores
    k_fattn<<<dim3(8, BB), 256, FATT_SMEM>>>(tm_qa, qkv, attn);
    // proj + residual + repbn1
    k_tgemm<<<dim3(256 / 128, MM / 128), 256, GEMM_SMEM>>>(tm_attn, tm_wproj, b_proj, t1,
        256, 256, 1, t, gamma1, beta1, rm1, rv1, alpha1, nullptr, nullptr);
    // FFN1 + SpatialSILU
    k_tgemm<<<dim3(CMID / 128, MM / 128), 256, GEMM_SMEM>>>(tm_t1, tm_w1, b1, hbuf,
        CMID, 256, 2, nullptr, nullptr, nullptr, nullptr, nullptr, nullptr, sa_w, sa_b);
    // FFN2 (wide) + residual + repbn2 -> [B,C,N]
    k_tgemm_w<<<MM / 128, 256, GEMMW_SMEM>>>(tm_h, tm_w2, b2, out,
        CMID, t1, gamma2, beta2, rm2, rv2, alpha2);
}